// round 15
// baseline (speedup 1.0000x reference)
#include <cuda_runtime.h>
#include <cuda.h>
#include <math.h>
#include <stdint.h>
#include <dlfcn.h>

#if defined(__CUDA_ARCH_FEAT_SM103_ALL) || defined(__CUDA_ARCH_FEAT_SM100_ALL) || defined(__CUDA_ARCH_FEAT_SM101_ALL) || defined(__CUDA_ARCH_FEAT_SM110_ALL)
#define HAS_TC 1
#else
#define HAS_TC 0
#endif

// Problem dims
constexpr int Bd = 8;
constexpr int Sd = 1024;
constexpr int Ed = 1024;
constexpr int Fd = 4096;
constexpr int MTOT = Bd * Sd;   // 8192

// cg2 tile: a 2-CTA cluster computes one 256x256 tile with single M=256 dispatches.
// Per CTA per stage: A half (128 rows x 128B) + B half (128 rows x 128B) = 32KB.
constexpr int TK = 32;          // K elems per stage
constexpr int NS = 6;           // pipeline stages (32KB each)
constexpr int STAGE_BYTES = 32768;
constexpr int SMEM_TOTAL = 1024 + NS * STAGE_BYTES;     // 197632
constexpr int NTHREADS = 192;   // 4 epilogue warps + 1 TMA warp + 1 MMA warp
constexpr int GRID = 128;       // 64 clusters of 2, persistent

// idesc cg2: c=F32(1), a=TF32(2), b=TF32(2), K-major, N=256, M=256
constexpr uint32_t IDESC2 =
    (1u << 4) | (2u << 7) | (2u << 10) | ((256 / 8) << 17) | ((256 / 16) << 24);

#define OFF_TMEM   0
#define OFF_FULL(s)  (8 + 8*(s))
#define OFF_EMPTY(s) (8 + 8*NS + 8*(s))
#define OFF_FIN      (8 + 16*NS)
#define OFF_TFREE    (8 + 16*NS + 8)

// ---------------- scratch (device globals) ---------------------------------
__device__ float g_xr  [(long long)MTOT * Ed];
__device__ float g_qk  [(long long)2 * MTOT * Ed];   // q | k contiguous
__device__ float g_vt  [(long long)MTOT * Ed];
__device__ float g_at  [(long long)Bd * Sd * Sd];
__device__ float g_ao  [(long long)MTOT * Ed];
__device__ float g_tmp [(long long)MTOT * Ed];
__device__ float g_h1  [(long long)MTOT * Ed];
__device__ float g_ff  [(long long)MTOT * Fd];
__device__ float g_wt  [(long long)3 * Ed * Ed];     // Wq^T | Wk^T | Wv^T
__device__ float g_b2  [2 * Ed];
__device__ float g_wdt [(long long)Ed * Ed];
__device__ float g_wit [(long long)Fd * Ed];
__device__ float g_wot [(long long)Ed * Fd];

// ---------------- PDL helpers ---------------------------------------------------
__device__ __forceinline__ void pdl_trigger() {
#if (defined(__CUDA_ARCH__) && __CUDA_ARCH__ >= 900)
    cudaTriggerProgrammaticLaunchCompletion();
#endif
}
__device__ __forceinline__ void pdl_wait() {
#if (defined(__CUDA_ARCH__) && __CUDA_ARCH__ >= 900)
    cudaGridDependencySynchronize();
#endif
}

// ---------------- PTX helpers -------------------------------------------------
__device__ __forceinline__ uint32_t smem_u32(const void* p) {
    uint32_t a;
    asm("{ .reg .u64 t; cvta.to.shared.u64 t, %1; cvt.u32.u64 %0, t; }" : "=r"(a) : "l"(p));
    return a;
}
__device__ __forceinline__ uint32_t elect_one() {
    uint32_t p;
    asm volatile("{ .reg .pred p; elect.sync _|p, 0xFFFFFFFF; selp.b32 %0,1,0,p; }" : "=r"(p));
    return p;
}
__device__ __forceinline__ uint32_t ctarank() {
    uint32_t r;
    asm("mov.u32 %0, %%cluster_ctarank;" : "=r"(r));
    return r;
}
__device__ __forceinline__ void cluster_sync() {
    asm volatile("barrier.cluster.arrive.aligned;" ::: "memory");
    asm volatile("barrier.cluster.wait.aligned;" ::: "memory");
}
__device__ __forceinline__ void mbar_init(uint32_t a, uint32_t c) {
    asm volatile("mbarrier.init.shared.b64 [%0], %1;" :: "r"(a), "r"(c) : "memory");
}
__device__ __forceinline__ void mbar_expect_tx(uint32_t a, uint32_t bytes) {
    asm volatile("mbarrier.arrive.expect_tx.shared.b64 _, [%0], %1;"
                 :: "r"(a), "r"(bytes) : "memory");
}
// Arrive on the same-offset mbarrier in cluster CTA 0 (leader).
__device__ __forceinline__ void mbar_arrive_leader(uint32_t a) {
    asm volatile(
        "{\n\t.reg .b32 ra;\n\t"
        "mapa.shared::cluster.u32 ra, %0, 0;\n\t"
        "mbarrier.arrive.shared::cluster.b64 _, [ra];\n\t}"
        :: "r"(a) : "memory");
}
__device__ __forceinline__ void mbar_wait(uint32_t a, uint32_t ph) {
    uint32_t done;
    asm volatile(
        "{\n\t.reg .pred p;\n\t"
        "mbarrier.try_wait.parity.acquire.cta.shared::cta.b64 p, [%1], %2;\n\t"
        "selp.b32 %0, 1, 0, p;\n\t}"
        : "=r"(done) : "r"(a), "r"(ph) : "memory");
    if (!done) {
        asm volatile(
            "{\n\t.reg .pred P1;\n\t"
            "WL%=:\n\t"
            "mbarrier.try_wait.parity.acquire.cta.shared::cta.b64 P1, [%0], %1, 0x989680;\n\t"
            "@P1 bra.uni WD%=;\n\t"
            "bra.uni WL%=;\n\t"
            "WD%=:\n\t}"
            :: "r"(a), "r"(ph) : "memory");
    }
}
// cg2 TMA 2D load: data to LOCAL smem, complete_tx to the LEADER's barrier
// (bit 24 cleared), per the validated TMA_LOAD_3D_CG2 pattern.
__device__ __forceinline__ void tma_cg2_2d(uint32_t dst, const void* map,
                                           int x, int y, uint32_t mbar) {
    asm volatile(
        "{\n\t.reg .b32 lb;\n\t"
        "and.b32 lb, %4, 0xFEFFFFFF;\n\t"
        "cp.async.bulk.tensor.2d.cta_group::2.shared::cluster.global.tile.mbarrier::complete_tx::bytes "
        "[%0], [%1, {%2, %3}], [lb];\n\t}"
        :: "r"(dst), "l"(map), "r"(x), "r"(y), "r"(mbar)
        : "memory");
}
__device__ __forceinline__ uint64_t make_desc(uint32_t addr) {
    return 0x4000404000010000ULL | ((uint64_t)(addr >> 4) & 0x3FFF);
}
__device__ __forceinline__ float rna_tf32(float x) {
    uint32_t u;
    asm("cvt.rna.tf32.f32 %0, %1;" : "=r"(u) : "f"(x));
    return __uint_as_float(u);
}

#if HAS_TC
__device__ __forceinline__ void mma_tf32_cg2(uint32_t d, uint64_t ad, uint64_t bd,
                                             uint32_t idesc, uint32_t en) {
    asm volatile(
        "{\n\t.reg .pred p;\n\t"
        "setp.ne.u32 p, %4, 0;\n\t"
        "tcgen05.mma.cta_group::2.kind::tf32 [%0], %1, %2, %3, "
        "{%5, %5, %5, %5, %5, %5, %5, %5}, p;\n\t}"
        :: "r"(d), "l"(ad), "l"(bd), "r"(idesc), "r"(en), "r"(0u)
        : "memory");
}
#define TC_ALLOC_CG2(sa, n)  asm volatile("tcgen05.alloc.cta_group::2.sync.aligned.shared::cta.b32 [%0], %1;" :: "r"(sa), "r"(n) : "memory")
#define TC_DEALLOC_CG2(t, n) asm volatile("tcgen05.dealloc.cta_group::2.sync.aligned.b32 %0, %1;" :: "r"(t), "r"(n))
#define TC_RELINQ_CG2()      asm volatile("tcgen05.relinquish_alloc_permit.cta_group::2.sync.aligned;")
#define TC_COMMIT_MC_CG2(mb) asm volatile("tcgen05.commit.cta_group::2.mbarrier::arrive::one.shared::cluster.multicast::cluster.b64 [%0], %1;" :: "r"(mb), "h"((uint16_t)0x3) : "memory")
#define TC_FENCE_AFTER()     asm volatile("tcgen05.fence::after_thread_sync;" ::: "memory")
#define TC_FENCE_BEFORE()    asm volatile("tcgen05.fence::before_thread_sync;" ::: "memory")
#define TC_WAIT_LD()         asm volatile("tcgen05.wait::ld.sync.aligned;" ::: "memory")

#define LDTM_X32(r, ta) \
    asm volatile( \
        "tcgen05.ld.sync.aligned.32x32b.x32.b32 " \
        "{%0, %1, %2, %3, %4, %5, %6, %7, " \
        " %8, %9, %10, %11, %12, %13, %14, %15, " \
        " %16, %17, %18, %19, %20, %21, %22, %23, " \
        " %24, %25, %26, %27, %28, %29, %30, %31}, [%32];" \
        : "=r"((r)[0]),  "=r"((r)[1]),  "=r"((r)[2]),  "=r"((r)[3]), \
          "=r"((r)[4]),  "=r"((r)[5]),  "=r"((r)[6]),  "=r"((r)[7]), \
          "=r"((r)[8]),  "=r"((r)[9]),  "=r"((r)[10]), "=r"((r)[11]), \
          "=r"((r)[12]), "=r"((r)[13]), "=r"((r)[14]), "=r"((r)[15]), \
          "=r"((r)[16]), "=r"((r)[17]), "=r"((r)[18]), "=r"((r)[19]), \
          "=r"((r)[20]), "=r"((r)[21]), "=r"((r)[22]), "=r"((r)[23]), \
          "=r"((r)[24]), "=r"((r)[25]), "=r"((r)[26]), "=r"((r)[27]), \
          "=r"((r)[28]), "=r"((r)[29]), "=r"((r)[30]), "=r"((r)[31]) \
        : "r"(ta))
#endif // HAS_TC

// ---------------- cg2 persistent warp-specialized TF32 GEMM --------------------
// One 256x256 tile per 2-CTA cluster. rank r supplies A rows [bm+r*128,+128) and
// B rows [bn+r*128,+128); HW composes M=256 x N=256 from both CTAs' halves, and
// each CTA's TMEM receives its own 128 M-rows x 256 cols of D.
// Producers: TMA-only (one elected thread/CTA); complete_tx -> leader FULL
// (count=1 = leader's expect_tx; tx = 65536 per stage).
// EMPTY/FIN: cg2 commit multicast (count 1 per CTA). TFREE on leader (count 2,
// one elected cross-CTA arrive per CTA after its epilogue drains).
template<int ACT, bool ROUND, bool BROW>
__global__ void __launch_bounds__(NTHREADS, 1)
tc_gemm(const __grid_constant__ CUtensorMap mapA,
        const __grid_constant__ CUtensorMap mapB,
        const float* __restrict__ bias, const float* __restrict__ resid,
        float* __restrict__ C, int K, int N, float alpha,
        long long sC, long long sBias,
        int arow0, int rA, int brow0, int rB,
        int TP, int gx, int pgxy)
{
#if HAS_TC
    extern __shared__ char smem[];
    const uint32_t sb = smem_u32(smem);
    const int tid = threadIdx.x;
    const int wid = tid >> 5;
    const int nk = K / TK;
    const int rank = (int)ctarank();

    if (tid == 0) {
        for (int s = 0; s < NS; s++) {
            mbar_init(sb + OFF_FULL(s), 1);     // leader's expect_tx
            mbar_init(sb + OFF_EMPTY(s), 1);    // cg2 commit multicast
        }
        mbar_init(sb + OFF_FIN, 1);             // cg2 commit multicast
        mbar_init(sb + OFF_TFREE, 2);           // one elected arrive per CTA
    }
    if (wid == 5) {
        TC_ALLOC_CG2(sb + OFF_TMEM, 256);
        TC_RELINQ_CG2();
    }
    __syncthreads();
    uint32_t tmem;
    asm volatile("ld.shared.b32 %0, [%1];" : "=r"(tmem) : "r"(sb + OFF_TMEM));

    cluster_sync();      // barriers + TMEM visible cluster-wide
    pdl_trigger();
    pdl_wait();

    if (tid < 128) {
        // ---- epilogue: this CTA's 128 M-rows x 256 cols from local TMEM ----
        const int lane = tid & 31;
        const int sp = wid;                 // 0..3
        int n = 0;
        for (int p = blockIdx.x >> 1; p < TP; p += (GRID / 2), n++) {
            mbar_wait(sb + OFF_FIN, n & 1);
            TC_FENCE_AFTER();
            const int tz = p / pgxy;
            const int rem = p - tz * pgxy;
            const int ty = rem / gx;
            const int tx = rem - ty * gx;
            const int bn = tx * 256;
            const long long rrowi = (long long)ty * 256 + rank * 128 + sp * 32 + lane;
            float* crow = C + (long long)tz * sC + rrowi * (long long)N + bn;
            const float* biasz = bias ? bias + (long long)tz * sBias : nullptr;
            const float* rres = resid ? resid + (long long)tz * sC + rrowi * (long long)N + bn
                                      : nullptr;
            float brv = 0.0f;
            if (BROW && biasz) brv = biasz[rrowi];

            #pragma unroll 1
            for (int cb = 0; cb < 8; cb++) {
                uint32_t r[32];
                LDTM_X32(r, tmem + cb * 32);
                TC_WAIT_LD();
                float v[32];
                #pragma unroll
                for (int j = 0; j < 32; j++) v[j] = __uint_as_float(r[j]) * alpha;
                if (biasz) {
                    if (BROW) {
                        #pragma unroll
                        for (int j = 0; j < 32; j++) v[j] += brv;
                    } else {
                        #pragma unroll
                        for (int j0 = 0; j0 < 32; j0 += 4) {
                            float4 bb = *reinterpret_cast<const float4*>(biasz + bn + cb * 32 + j0);
                            v[j0+0] += bb.x; v[j0+1] += bb.y; v[j0+2] += bb.z; v[j0+3] += bb.w;
                        }
                    }
                }
                if (rres) {
                    #pragma unroll
                    for (int j0 = 0; j0 < 32; j0 += 4) {
                        float4 rv = *reinterpret_cast<const float4*>(rres + cb * 32 + j0);
                        v[j0+0] += rv.x; v[j0+1] += rv.y; v[j0+2] += rv.z; v[j0+3] += rv.w;
                    }
                }
                if constexpr (ACT == 1) {
                    #pragma unroll
                    for (int j = 0; j < 32; j++)
                        v[j] = 0.5f * v[j] * (1.0f + erff(v[j] * 0.70710678118654752f));
                }
                if constexpr (ROUND) {
                    #pragma unroll
                    for (int j = 0; j < 32; j++) v[j] = rna_tf32(v[j]);
                }
                #pragma unroll
                for (int j0 = 0; j0 < 32; j0 += 4) {
                    float4 o; o.x = v[j0]; o.y = v[j0+1]; o.z = v[j0+2]; o.w = v[j0+3];
                    *reinterpret_cast<float4*>(crow + cb * 32 + j0) = o;
                }
            }
            TC_FENCE_BEFORE();
            asm volatile("bar.sync 1, 128;" ::: "memory");
            if (tid == 0) mbar_arrive_leader(sb + OFF_TFREE);
        }
    } else if (tid < 160) {
        // ---- TMA producer warp (one elected thread per CTA) ----
        if (elect_one()) {
            int s = 0; uint32_t eph = 1;
            for (int p = blockIdx.x >> 1; p < TP; p += (GRID / 2)) {
                const int tz = p / pgxy;
                const int rem = p - tz * pgxy;
                const int ty = rem / gx;
                const int tx = rem - ty * gx;
                const int ar = arow0 + rA * tz + ty * 256 + rank * 128;
                const int br = brow0 + rB * tz + tx * 256 + rank * 128;
                for (int kt = 0; kt < nk; kt++) {
                    mbar_wait(sb + OFF_EMPTY(s), eph);
                    const uint32_t st = sb + 1024 + s * STAGE_BYTES;
                    if (rank == 0) mbar_expect_tx(sb + OFF_FULL(s), 65536);
                    tma_cg2_2d(st,         &mapA, kt * TK, ar, sb + OFF_FULL(s));
                    tma_cg2_2d(st + 16384, &mapB, kt * TK, br, sb + OFF_FULL(s));
                    if (++s == NS) { s = 0; eph ^= 1; }
                }
            }
        }
    } else {
        // ---- MMA issuer warp (leader CTA only) ----
        if (rank == 0) {
            uint32_t ep = elect_one();
            int s = 0; uint32_t ph = 0; int n = 0;
            for (int p = blockIdx.x >> 1; p < TP; p += (GRID / 2), n++) {
                mbar_wait(sb + OFF_TFREE, (n + 1) & 1);
                TC_FENCE_AFTER();
                for (int kt = 0; kt < nk; kt++) {
                    mbar_wait(sb + OFF_FULL(s), ph);
                    if (ep) {
                        const uint32_t st = sb + 1024 + s * STAGE_BYTES;
                        uint64_t ad = make_desc(st);
                        uint64_t bd = make_desc(st + 16384);
                        const uint32_t en0 = (uint32_t)(kt != 0);
                        #pragma unroll
                        for (int j = 0; j < 4; j++)
                            mma_tf32_cg2(tmem, ad + 2 * j, bd + 2 * j, IDESC2,
                                         en0 | (uint32_t)(j != 0));
                        TC_COMMIT_MC_CG2(sb + OFF_EMPTY(s));
                        if (kt == nk - 1) TC_COMMIT_MC_CG2(sb + OFF_FIN);
                    }
                    if (++s == NS) { s = 0; ph ^= 1; }
                }
            }
        }
    }

    __syncthreads();
    cluster_sync();      // no CTA exits while peer may still touch its smem/TMEM
    if (wid == 5) TC_DEALLOC_CG2(tmem, 256);
#endif // HAS_TC
}

// ---------------- elementwise kernels ---------------------------------------
__device__ __forceinline__ float block_sum(float v, float* sh) {
    const int lane = threadIdx.x & 31, w = threadIdx.x >> 5;
    #pragma unroll
    for (int o = 16; o; o >>= 1) v += __shfl_xor_sync(0xffffffffu, v, o);
    __syncthreads();
    if (lane == 0) sh[w] = v;
    __syncthreads();
    float s = 0.f;
    #pragma unroll
    for (int i = 0; i < 8; i++) s += sh[i];
    return s;
}
__device__ __forceinline__ float block_max(float v, float* sh) {
    const int lane = threadIdx.x & 31, w = threadIdx.x >> 5;
    #pragma unroll
    for (int o = 16; o; o >>= 1) v = fmaxf(v, __shfl_xor_sync(0xffffffffu, v, o));
    __syncthreads();
    if (lane == 0) sh[w] = v;
    __syncthreads();
    float s = -INFINITY;
    #pragma unroll
    for (int i = 0; i < 8; i++) s = fmaxf(s, sh[i]);
    return s;
}

__global__ void __launch_bounds__(256) softmax_kernel(float* __restrict__ data)
{
    __shared__ float sh[8];
    pdl_trigger();
    pdl_wait();
    const long long row = blockIdx.x;
    float4* p = reinterpret_cast<float4*>(data + row * 1024);
    float4 x = p[threadIdx.x];
    float m = fmaxf(fmaxf(x.x, x.y), fmaxf(x.z, x.w));
    m = block_max(m, sh);
    x.x = expf(x.x - m); x.y = expf(x.y - m);
    x.z = expf(x.z - m); x.w = expf(x.w - m);
    float s = x.x + x.y + x.z + x.w;
    s = block_sum(s, sh);
    const float inv = 1.0f / s;
    x.x = rna_tf32(x.x * inv); x.y = rna_tf32(x.y * inv);
    x.z = rna_tf32(x.z * inv); x.w = rna_tf32(x.w * inv);
    p[threadIdx.x] = x;
}

template<bool ROUND>
__global__ void __launch_bounds__(256)
ln_kernel(const float* __restrict__ in, const float* __restrict__ g,
          const float* __restrict__ b, float* __restrict__ out)
{
    __shared__ float sh[8];
    pdl_trigger();
    pdl_wait();
    const long long row = blockIdx.x;
    const float4* p = reinterpret_cast<const float4*>(in + row * 1024);
    float4 x = p[threadIdx.x];
    float s = x.x + x.y + x.z + x.w;
    s = block_sum(s, sh);
    const float mu = s * (1.0f / 1024.0f);
    const float dx = x.x - mu, dy = x.y - mu, dz = x.z - mu, dw = x.w - mu;
    float ss = dx * dx + dy * dy + dz * dz + dw * dw;
    ss = block_sum(ss, sh);
    const float rstd = rsqrtf(ss * (1.0f / 1024.0f) + 1e-12f);
    const float4 gg = reinterpret_cast<const float4*>(g)[threadIdx.x];
    const float4 bb = reinterpret_cast<const float4*>(b)[threadIdx.x];
    float4 o;
    o.x = dx * rstd * gg.x + bb.x;
    o.y = dy * rstd * gg.y + bb.y;
    o.z = dz * rstd * gg.z + bb.z;
    o.w = dw * rstd * gg.w + bb.w;
    if (ROUND) { o.x = rna_tf32(o.x); o.y = rna_tf32(o.y); o.z = rna_tf32(o.z); o.w = rna_tf32(o.w); }
    reinterpret_cast<float4*>(out + row * 1024)[threadIdx.x] = o;
}

// Fast 64x64 transpose body.
__device__ __forceinline__ void transpose_body(const float* __restrict__ in,
                                               float* __restrict__ out,
                                               int R, int C, int r0, int c0)
{
    __shared__ float t[64][65];
    const int fc = (threadIdx.x & 15) * 4;
    const int fr = threadIdx.x >> 4;

    #pragma unroll
    for (int i = 0; i < 4; i++) {
        const int r = fr + i * 16;
        float4 x = *reinterpret_cast<const float4*>(in + (long long)(r0 + r) * C + c0 + fc);
        t[fc + 0][r] = x.x; t[fc + 1][r] = x.y; t[fc + 2][r] = x.z; t[fc + 3][r] = x.w;
    }
    __syncthreads();
    #pragma unroll
    for (int i = 0; i < 4; i++) {
        const int oc = fr + i * 16;
        float4 y;
        y.x = rna_tf32(t[oc][fc + 0]); y.y = rna_tf32(t[oc][fc + 1]);
        y.z = rna_tf32(t[oc][fc + 2]); y.w = rna_tf32(t[oc][fc + 3]);
        *reinterpret_cast<float4*>(out + (long long)(c0 + oc) * R + r0 + fc) = y;
    }
}

__global__ void __launch_bounds__(256)
prep1_kernel(const float4* __restrict__ x, float4* __restrict__ xr, long long n4,
             const float4* __restrict__ bq, const float4* __restrict__ bk, float4* __restrict__ b2,
             const float* __restrict__ Wq, const float* __restrict__ Wk,
             const float* __restrict__ Wv, const float* __restrict__ Wd,
             float* __restrict__ oq, float* __restrict__ ok,
             float* __restrict__ ov, float* __restrict__ od)
{
    pdl_trigger();
    const int b = blockIdx.x;
    if (b < 1024) {
        for (long long i = b * 256LL + threadIdx.x; i < n4; i += 1024LL * 256LL) {
            float4 v = x[i];
            v.x = rna_tf32(v.x); v.y = rna_tf32(v.y);
            v.z = rna_tf32(v.z); v.w = rna_tf32(v.w);
            xr[i] = v;
        }
    } else if (b < 1026) {
        const float4* src = (b == 1024) ? bq : bk;
        b2[(b - 1024) * 256 + threadIdx.x] = src[threadIdx.x];
    } else {
        const int idx = b - 1026;
        const int w = idx >> 8;
        const int r = (idx & 255) >> 4;
        const int c = idx & 15;
        const float* in = w == 0 ? Wq : w == 1 ? Wk : w == 2 ? Wv : Wd;
        float* out      = w == 0 ? oq : w == 1 ? ok : w == 2 ? ov : od;
        transpose_body(in, out, 1024, 1024, r * 64, c * 64);
    }
}

__global__ void __launch_bounds__(256)
prep2_kernel(const float* __restrict__ Wi, float* __restrict__ wit,
             const float* __restrict__ Wo, float* __restrict__ wot)
{
    pdl_trigger();
    const int b = blockIdx.x;
    if (b < 1024) {
        const int cx = b & 63, ry = b >> 6;
        transpose_body(Wi, wit, Ed, Fd, ry * 64, cx * 64);
    } else {
        const int idx = b - 1024;
        const int cx = idx & 15, ry = idx >> 4;
        transpose_body(Wo, wot, Fd, Ed, ry * 64, cx * 64);
    }
}

// ---------------- host launcher -----------------------------------------------
typedef CUresult (*PFN_encode)(CUtensorMap*, CUtensorMapDataType, cuuint32_t, void*,
                               const cuuint64_t*, const cuuint64_t*, const cuuint32_t*,
                               const cuuint32_t*, CUtensorMapInterleave, CUtensorMapSwizzle,
                               CUtensorMapL2promotion, CUtensorMapFloatOOBfill);

static void enc2d(PFN_encode f, CUtensorMap* m, void* base, cuuint64_t K, cuuint64_t rows)
{
    cuuint64_t dims[2]    = {K, rows};
    cuuint64_t strides[1] = {K * 4};
    cuuint32_t box[2]     = {32, 128};
    cuuint32_t es[2]      = {1, 1};
    f(m, CU_TENSOR_MAP_DATA_TYPE_FLOAT32, 2, base, dims, strides, box, es,
      CU_TENSOR_MAP_INTERLEAVE_NONE, CU_TENSOR_MAP_SWIZZLE_128B,
      CU_TENSOR_MAP_L2_PROMOTION_L2_128B, CU_TENSOR_MAP_FLOAT_OOB_FILL_NONE);
}

extern "C" void kernel_launch(void* const* d_in, const int* in_sizes, int n_in,
                              void* d_out, int out_size)
{
    const float* x  = (const float*)d_in[0];
    const float* Wq = (const float*)d_in[1];
    const float* bq = (const float*)d_in[2];
    const float* Wk = (const float*)d_in[3];
    const float* bk = (const float*)d_in[4];
    const float* Wv = (const float*)d_in[5];
    const float* bv = (const float*)d_in[6];
    const float* Wd = (const float*)d_in[7];
    const float* bd = (const float*)d_in[8];
    const float* g1 = (const float*)d_in[9];
    const float* b1 = (const float*)d_in[10];
    const float* Wi = (const float*)d_in[11];
    const float* bi = (const float*)d_in[12];
    const float* Wo = (const float*)d_in[13];
    const float* bo = (const float*)d_in[14];
    const float* g2 = (const float*)d_in[15];
    const float* b2 = (const float*)d_in[16];
    float* out = (float*)d_out;

    float *xr, *qk, *vt, *at, *ao, *tmp, *h1, *ff;
    float *wt, *b2qk, *wdt, *wit, *wot;
    cudaGetSymbolAddress((void**)&xr,   g_xr);
    cudaGetSymbolAddress((void**)&qk,   g_qk);
    cudaGetSymbolAddress((void**)&vt,   g_vt);
    cudaGetSymbolAddress((void**)&at,   g_at);
    cudaGetSymbolAddress((void**)&ao,   g_ao);
    cudaGetSymbolAddress((void**)&tmp,  g_tmp);
    cudaGetSymbolAddress((void**)&h1,   g_h1);
    cudaGetSymbolAddress((void**)&ff,   g_ff);
    cudaGetSymbolAddress((void**)&wt,   g_wt);
    cudaGetSymbolAddress((void**)&b2qk, g_b2);
    cudaGetSymbolAddress((void**)&wdt,  g_wdt);
    cudaGetSymbolAddress((void**)&wit,  g_wit);
    cudaGetSymbolAddress((void**)&wot,  g_wot);

    cudaFuncSetAttribute(tc_gemm<0, true,  false>, cudaFuncAttributeMaxDynamicSharedMemorySize, SMEM_TOTAL);
    cudaFuncSetAttribute(tc_gemm<0, true,  true >, cudaFuncAttributeMaxDynamicSharedMemorySize, SMEM_TOTAL);
    cudaFuncSetAttribute(tc_gemm<0, false, false>, cudaFuncAttributeMaxDynamicSharedMemorySize, SMEM_TOTAL);
    cudaFuncSetAttribute(tc_gemm<1, true,  false>, cudaFuncAttributeMaxDynamicSharedMemorySize, SMEM_TOTAL);

    const long long ME = (long long)MTOT * Ed;
    const long long SE = (long long)Sd * Ed;
    const long long SS = (long long)Sd * Sd;
    const long long EE = (long long)Ed * Ed;

    // Tensormaps (driver API via dlopen)
    void* hdl = dlopen("libcuda.so.1", RTLD_LAZY | RTLD_GLOBAL);
    if (!hdl) hdl = dlopen("libcuda.so", RTLD_LAZY | RTLD_GLOBAL);
    PFN_encode enc = hdl ? (PFN_encode)dlsym(hdl, "cuTensorMapEncodeTiled") : nullptr;
    CUtensorMap mXr{}, mWt{}, mQk{}, mVt{}, mAt{}, mAo{}, mWdt{}, mH1{}, mWit{}, mFf{}, mWot{};
    enc2d(enc, &mXr,  xr,  1024, 8192);
    enc2d(enc, &mWt,  wt,  1024, 3072);
    enc2d(enc, &mQk,  qk,  1024, 16384);
    enc2d(enc, &mVt,  vt,  1024, 8192);
    enc2d(enc, &mAt,  at,  1024, 8192);
    enc2d(enc, &mAo,  ao,  1024, 8192);
    enc2d(enc, &mWdt, wdt, 1024, 1024);
    enc2d(enc, &mH1,  h1,  1024, 8192);
    enc2d(enc, &mWit, wit, 1024, 4096);
    enc2d(enc, &mFf,  ff,  4096, 8192);
    enc2d(enc, &mWot, wot, 4096, 1024);

    cudaLaunchAttribute pdlAttr[1];
    pdlAttr[0].id = cudaLaunchAttributeProgrammaticStreamSerialization;
    pdlAttr[0].val.programmaticStreamSerializationAllowed = 1;

    cudaLaunchAttribute clAttr[1];
    clAttr[0].id = cudaLaunchAttributeClusterDimension;
    clAttr[0].val.clusterDim.x = 2;
    clAttr[0].val.clusterDim.y = 1;
    clAttr[0].val.clusterDim.z = 1;

    auto launch = [&](auto kern, dim3 g, dim3 b, size_t sm,
                      cudaLaunchAttribute* attrs, int na, auto... args) {
        cudaLaunchConfig_t cfg{};
        cfg.gridDim = g; cfg.blockDim = b;
        cfg.dynamicSmemBytes = sm;
        cfg.stream = 0;
        cfg.attrs = attrs;
        cfg.numAttrs = na;
        cudaLaunchKernelEx(&cfg, kern, args...);
    };

    const float* nullf = nullptr;
    const dim3 gg(GRID);
    const dim3 gt(NTHREADS);

    // 0: prep1
    launch(prep1_kernel, dim3(2050), dim3(256), 0, nullptr, 0,
           (const float4*)x, (float4*)xr, (long long)(ME / 4),
           (const float4*)bq, (const float4*)bk, (float4*)b2qk,
           Wq, Wk, Wv, Wd, wt, wt + EE, wt + 2 * EE, wdt);
    // 1: prep2 (PDL co-run)
    launch(prep2_kernel, dim3(2048), dim3(256), 0, pdlAttr, 1, Wi, wit, Wo, wot);
    // 2: QK projections. A=xr (z: 0), B=wt (z: rB=1024 selects Wq^T/Wk^T). T=256 tiles.
    launch(tc_gemm<0, true, false>, gg, gt, (size_t)SMEM_TOTAL, clAttr, 1,
           mXr, mWt, (const float*)b2qk, nullf, qk,
           (int)Ed, (int)Ed, 1.0f, ME, (long long)Ed, 0, 0, 0, 1024, 256, 4, 128);
    // 3: V^T = Wv^T @ xr^T + bv(row). A=wt rows[2048..], B=xr batched. T=128.
    launch(tc_gemm<0, true, true>, gg, gt, (size_t)SMEM_TOTAL, clAttr, 1,
           mWt, mXr, bv, nullf, vt,
           (int)Ed, (int)Sd, 1.0f, SE, 0LL, 2048, 0, 0, 1024, 128, 4, 16);
    // 4: scores = q @ k^T / 32. A=q (qk rows [0,8192)), B=k (rows [8192,16384)). T=128.
    launch(tc_gemm<0, false, false>, gg, gt, (size_t)SMEM_TOTAL, clAttr, 1,
           mQk, mQk, nullf, nullf, at,
           (int)Ed, (int)Sd, 0.03125f, SS, 0LL, 0, 1024, 8192, 1024, 128, 4, 16);
    // 5: softmax
    launch(softmax_kernel, dim3(Bd * Sd), dim3(256), 0, pdlAttr, 1, at);
    // 6: attn_out = attn_w @ v. A=at, B=vt, both batched. T=128. K=Sd.
    launch(tc_gemm<0, true, false>, gg, gt, (size_t)SMEM_TOTAL, clAttr, 1,
           mAt, mVt, nullf, nullf, ao,
           (int)Sd, (int)Ed, 1.0f, SE, 0LL, 0, 1024, 0, 1024, 128, 4, 16);
    // 7: tmp = ao @ Wd + bd + x. T=128.
    launch(tc_gemm<0, false, false>, gg, gt, (size_t)SMEM_TOTAL, clAttr, 1,
           mAo, mWdt, bd, x, tmp,
           (int)Ed, (int)Ed, 1.0f, 0LL, 0LL, 0, 0, 0, 0, 128, 4, 128);
    // 8: h1 = LN(tmp)
    launch(ln_kernel<true>, dim3(MTOT), dim3(256), 0, pdlAttr, 1,
           (const float*)tmp, g1, b1, h1);
    // 9: ff = gelu(h1 @ Wi + bi). T=512.
    launch(tc_gemm<1, true, false>, gg, gt, (size_t)SMEM_TOTAL, clAttr, 1,
           mH1, mWit, bi, nullf, ff,
           (int)Ed, (int)Fd, 1.0f, 0LL, 0LL, 0, 0, 0, 0, 512, 16, 512);
    // 10: tmp = ff @ Wo + bo + h1. K=4096, T=128.
    launch(tc_gemm<0, false, false>, gg, gt, (size_t)SMEM_TOTAL, clAttr, 1,
           mFf, mWot, bo, (const float*)h1, tmp,
           (int)Fd, (int)Ed, 1.0f, 0LL, 0LL, 0, 0, 0, 0, 128, 4, 128);
    // 11: out = LN(tmp)
    launch(ln_kernel<false>, dim3(MTOT), dim3(256), 0, pdlAttr, 1,
           (const float*)tmp, g2, b2, out);
}

// round 16
// speedup vs baseline: 1.1732x; 1.1732x over previous
#include <cuda_runtime.h>
#include <cuda.h>
#include <math.h>
#include <stdint.h>
#include <dlfcn.h>

#if defined(__CUDA_ARCH_FEAT_SM103_ALL) || defined(__CUDA_ARCH_FEAT_SM100_ALL) || defined(__CUDA_ARCH_FEAT_SM101_ALL) || defined(__CUDA_ARCH_FEAT_SM110_ALL)
#define HAS_TC 1
#else
#define HAS_TC 0
#endif

// Problem dims
constexpr int Bd = 8;
constexpr int Sd = 1024;
constexpr int Ed = 1024;
constexpr int Fd = 4096;
constexpr int MTOT = Bd * Sd;   // 8192

// cg2 tile: a 2-CTA cluster computes one 256x256 tile; single M=256 dispatches.
// TK=64: per CTA per stage = A half (2x16KB panels) + B half (2x16KB) = 64KB.
constexpr int TK = 64;          // K elems per stage (two 128B SW128 panels)
constexpr int NS = 3;           // pipeline stages (64KB each)
constexpr int STAGE_BYTES = 65536;
constexpr int SMEM_TOTAL = 1024 + NS * STAGE_BYTES;     // 197632
constexpr int NTHREADS = 192;   // 4 epilogue warps + 1 TMA warp + 1 MMA warp
constexpr int GRID = 128;       // 64 clusters of 2, persistent

// idesc cg2: c=F32(1), a=TF32(2), b=TF32(2), K-major, N=256, M=256
constexpr uint32_t IDESC2 =
    (1u << 4) | (2u << 7) | (2u << 10) | ((256 / 8) << 17) | ((256 / 16) << 24);

#define OFF_TMEM   0
#define OFF_FULL(s)   (8 + 8*(s))
#define OFF_EMPTY(s)  (8 + 8*NS + 8*(s))
#define OFF_FIN(b)    (8 + 16*NS + 8*(b))
#define OFF_TFREE(b)  (8 + 16*NS + 16 + 8*(b))

// ---------------- scratch (device globals) ---------------------------------
__device__ float g_xr  [(long long)MTOT * Ed];
__device__ float g_qk  [(long long)2 * MTOT * Ed];   // q | k contiguous
__device__ float g_vt  [(long long)MTOT * Ed];
__device__ float g_at  [(long long)Bd * Sd * Sd];
__device__ float g_ao  [(long long)MTOT * Ed];
__device__ float g_tmp [(long long)MTOT * Ed];
__device__ float g_h1  [(long long)MTOT * Ed];
__device__ float g_ff  [(long long)MTOT * Fd];
__device__ float g_wt  [(long long)3 * Ed * Ed];     // Wq^T | Wk^T | Wv^T
__device__ float g_b2  [2 * Ed];
__device__ float g_wdt [(long long)Ed * Ed];
__device__ float g_wit [(long long)Fd * Ed];
__device__ float g_wot [(long long)Ed * Fd];

// ---------------- PDL helpers ---------------------------------------------------
__device__ __forceinline__ void pdl_trigger() {
#if (defined(__CUDA_ARCH__) && __CUDA_ARCH__ >= 900)
    cudaTriggerProgrammaticLaunchCompletion();
#endif
}
__device__ __forceinline__ void pdl_wait() {
#if (defined(__CUDA_ARCH__) && __CUDA_ARCH__ >= 900)
    cudaGridDependencySynchronize();
#endif
}

// ---------------- PTX helpers -------------------------------------------------
__device__ __forceinline__ uint32_t smem_u32(const void* p) {
    uint32_t a;
    asm("{ .reg .u64 t; cvta.to.shared.u64 t, %1; cvt.u32.u64 %0, t; }" : "=r"(a) : "l"(p));
    return a;
}
__device__ __forceinline__ uint32_t elect_one() {
    uint32_t p;
    asm volatile("{ .reg .pred p; elect.sync _|p, 0xFFFFFFFF; selp.b32 %0,1,0,p; }" : "=r"(p));
    return p;
}
__device__ __forceinline__ uint32_t ctarank() {
    uint32_t r;
    asm("mov.u32 %0, %%cluster_ctarank;" : "=r"(r));
    return r;
}
__device__ __forceinline__ void cluster_sync() {
    asm volatile("barrier.cluster.arrive.aligned;" ::: "memory");
    asm volatile("barrier.cluster.wait.aligned;" ::: "memory");
}
__device__ __forceinline__ void mbar_init(uint32_t a, uint32_t c) {
    asm volatile("mbarrier.init.shared.b64 [%0], %1;" :: "r"(a), "r"(c) : "memory");
}
__device__ __forceinline__ void mbar_expect_tx(uint32_t a, uint32_t bytes) {
    asm volatile("mbarrier.arrive.expect_tx.shared.b64 _, [%0], %1;"
                 :: "r"(a), "r"(bytes) : "memory");
}
// Arrive on the same-offset mbarrier in cluster CTA 0 (leader).
__device__ __forceinline__ void mbar_arrive_leader(uint32_t a) {
    asm volatile(
        "{\n\t.reg .b32 ra;\n\t"
        "mapa.shared::cluster.u32 ra, %0, 0;\n\t"
        "mbarrier.arrive.shared::cluster.b64 _, [ra];\n\t}"
        :: "r"(a) : "memory");
}
__device__ __forceinline__ void mbar_wait(uint32_t a, uint32_t ph) {
    uint32_t done;
    asm volatile(
        "{\n\t.reg .pred p;\n\t"
        "mbarrier.try_wait.parity.acquire.cta.shared::cta.b64 p, [%1], %2;\n\t"
        "selp.b32 %0, 1, 0, p;\n\t}"
        : "=r"(done) : "r"(a), "r"(ph) : "memory");
    if (!done) {
        asm volatile(
            "{\n\t.reg .pred P1;\n\t"
            "WL%=:\n\t"
            "mbarrier.try_wait.parity.acquire.cta.shared::cta.b64 P1, [%0], %1, 0x989680;\n\t"
            "@P1 bra.uni WD%=;\n\t"
            "bra.uni WL%=;\n\t"
            "WD%=:\n\t}"
            :: "r"(a), "r"(ph) : "memory");
    }
}
// cg2 TMA 2D load: data to LOCAL smem, complete_tx to the LEADER's barrier
// (bit 24 cleared), per the validated TMA_LOAD_3D_CG2 pattern.
__device__ __forceinline__ void tma_cg2_2d(uint32_t dst, const void* map,
                                           int x, int y, uint32_t mbar) {
    asm volatile(
        "{\n\t.reg .b32 lb;\n\t"
        "and.b32 lb, %4, 0xFEFFFFFF;\n\t"
        "cp.async.bulk.tensor.2d.cta_group::2.shared::cluster.global.tile.mbarrier::complete_tx::bytes "
        "[%0], [%1, {%2, %3}], [lb];\n\t}"
        :: "r"(dst), "l"(map), "r"(x), "r"(y), "r"(mbar)
        : "memory");
}
__device__ __forceinline__ uint64_t make_desc(uint32_t addr) {
    return 0x4000404000010000ULL | ((uint64_t)(addr >> 4) & 0x3FFF);
}
__device__ __forceinline__ float rna_tf32(float x) {
    uint32_t u;
    asm("cvt.rna.tf32.f32 %0, %1;" : "=r"(u) : "f"(x));
    return __uint_as_float(u);
}

#if HAS_TC
__device__ __forceinline__ void mma_tf32_cg2(uint32_t d, uint64_t ad, uint64_t bd,
                                             uint32_t idesc, uint32_t en) {
    asm volatile(
        "{\n\t.reg .pred p;\n\t"
        "setp.ne.u32 p, %4, 0;\n\t"
        "tcgen05.mma.cta_group::2.kind::tf32 [%0], %1, %2, %3, "
        "{%5, %5, %5, %5, %5, %5, %5, %5}, p;\n\t}"
        :: "r"(d), "l"(ad), "l"(bd), "r"(idesc), "r"(en), "r"(0u)
        : "memory");
}
#define TC_ALLOC_CG2(sa, n)  asm volatile("tcgen05.alloc.cta_group::2.sync.aligned.shared::cta.b32 [%0], %1;" :: "r"(sa), "r"(n) : "memory")
#define TC_DEALLOC_CG2(t, n) asm volatile("tcgen05.dealloc.cta_group::2.sync.aligned.b32 %0, %1;" :: "r"(t), "r"(n))
#define TC_RELINQ_CG2()      asm volatile("tcgen05.relinquish_alloc_permit.cta_group::2.sync.aligned;")
#define TC_COMMIT_MC_CG2(mb) asm volatile("tcgen05.commit.cta_group::2.mbarrier::arrive::one.shared::cluster.multicast::cluster.b64 [%0], %1;" :: "r"(mb), "h"((uint16_t)0x3) : "memory")
#define TC_FENCE_AFTER()     asm volatile("tcgen05.fence::after_thread_sync;" ::: "memory")
#define TC_FENCE_BEFORE()    asm volatile("tcgen05.fence::before_thread_sync;" ::: "memory")
#define TC_WAIT_LD()         asm volatile("tcgen05.wait::ld.sync.aligned;" ::: "memory")

#define LDTM_X32(r, ta) \
    asm volatile( \
        "tcgen05.ld.sync.aligned.32x32b.x32.b32 " \
        "{%0, %1, %2, %3, %4, %5, %6, %7, " \
        " %8, %9, %10, %11, %12, %13, %14, %15, " \
        " %16, %17, %18, %19, %20, %21, %22, %23, " \
        " %24, %25, %26, %27, %28, %29, %30, %31}, [%32];" \
        : "=r"((r)[0]),  "=r"((r)[1]),  "=r"((r)[2]),  "=r"((r)[3]), \
          "=r"((r)[4]),  "=r"((r)[5]),  "=r"((r)[6]),  "=r"((r)[7]), \
          "=r"((r)[8]),  "=r"((r)[9]),  "=r"((r)[10]), "=r"((r)[11]), \
          "=r"((r)[12]), "=r"((r)[13]), "=r"((r)[14]), "=r"((r)[15]), \
          "=r"((r)[16]), "=r"((r)[17]), "=r"((r)[18]), "=r"((r)[19]), \
          "=r"((r)[20]), "=r"((r)[21]), "=r"((r)[22]), "=r"((r)[23]), \
          "=r"((r)[24]), "=r"((r)[25]), "=r"((r)[26]), "=r"((r)[27]), \
          "=r"((r)[28]), "=r"((r)[29]), "=r"((r)[30]), "=r"((r)[31]) \
        : "r"(ta))
#endif // HAS_TC

// ---------------- cg2 persistent warp-specialized TF32 GEMM --------------------
// One 256x256 tile per 2-CTA cluster; TK=64 stages; TMEM D ping-pong (2 banks).
// Producers: TMA-only, 4 box-{32,128} loads per CTA per stage; complete_tx ->
// leader FULL (count=1 = leader expect_tx; tx = 131072 cluster-wide per stage).
// EMPTY: cg2 commit multicast each stage. FIN[bank]: cg2 commit multicast at tile
// end. TFREE[bank] on leader (count 2): epilogues release a D bank after drain,
// so tile n+1's MMA (other bank) overlaps tile n's drain.
template<int ACT, bool ROUND, bool BROW>
__global__ void __launch_bounds__(NTHREADS, 1)
tc_gemm(const __grid_constant__ CUtensorMap mapA,
        const __grid_constant__ CUtensorMap mapB,
        const float* __restrict__ bias, const float* __restrict__ resid,
        float* __restrict__ C, int K, int N, float alpha,
        long long sC, long long sBias,
        int arow0, int rA, int brow0, int rB,
        int TP, int gx, int pgxy)
{
#if HAS_TC
    extern __shared__ char smem[];
    const uint32_t sb = smem_u32(smem);
    const int tid = threadIdx.x;
    const int wid = tid >> 5;
    const int nk = K / TK;
    const int rank = (int)ctarank();

    if (tid == 0) {
        for (int s = 0; s < NS; s++) {
            mbar_init(sb + OFF_FULL(s), 1);     // leader's expect_tx
            mbar_init(sb + OFF_EMPTY(s), 1);    // cg2 commit multicast
        }
        mbar_init(sb + OFF_FIN(0), 1);
        mbar_init(sb + OFF_FIN(1), 1);
        mbar_init(sb + OFF_TFREE(0), 2);
        mbar_init(sb + OFF_TFREE(1), 2);
    }
    if (wid == 5) {
        TC_ALLOC_CG2(sb + OFF_TMEM, 512);       // 2 x 256-col D banks
        TC_RELINQ_CG2();
    }
    __syncthreads();
    uint32_t tmem;
    asm volatile("ld.shared.b32 %0, [%1];" : "=r"(tmem) : "r"(sb + OFF_TMEM));

    cluster_sync();      // barriers + TMEM visible cluster-wide
    pdl_trigger();
    pdl_wait();

    if (tid < 128) {
        // ---- epilogue: this CTA's 128 M-rows x 256 cols from bank (n&1) ----
        const int lane = tid & 31;
        const int sp = wid;                 // 0..3
        int n = 0;
        for (int p = blockIdx.x >> 1; p < TP; p += (GRID / 2), n++) {
            const int bank = n & 1, nb = n >> 1;
            mbar_wait(sb + OFF_FIN(bank), nb & 1);
            TC_FENCE_AFTER();
            const int tz = p / pgxy;
            const int rem = p - tz * pgxy;
            const int ty = rem / gx;
            const int tx = rem - ty * gx;
            const int bn = tx * 256;
            const long long rrowi = (long long)ty * 256 + rank * 128 + sp * 32 + lane;
            float* crow = C + (long long)tz * sC + rrowi * (long long)N + bn;
            const float* biasz = bias ? bias + (long long)tz * sBias : nullptr;
            const float* rres = resid ? resid + (long long)tz * sC + rrowi * (long long)N + bn
                                      : nullptr;
            float brv = 0.0f;
            if (BROW && biasz) brv = biasz[rrowi];
            const uint32_t tmb = tmem + bank * 256;

            #pragma unroll 1
            for (int cb = 0; cb < 8; cb++) {
                uint32_t r[32];
                LDTM_X32(r, tmb + cb * 32);
                TC_WAIT_LD();
                float v[32];
                #pragma unroll
                for (int j = 0; j < 32; j++) v[j] = __uint_as_float(r[j]) * alpha;
                if (biasz) {
                    if (BROW) {
                        #pragma unroll
                        for (int j = 0; j < 32; j++) v[j] += brv;
                    } else {
                        #pragma unroll
                        for (int j0 = 0; j0 < 32; j0 += 4) {
                            float4 bb = *reinterpret_cast<const float4*>(biasz + bn + cb * 32 + j0);
                            v[j0+0] += bb.x; v[j0+1] += bb.y; v[j0+2] += bb.z; v[j0+3] += bb.w;
                        }
                    }
                }
                if (rres) {
                    #pragma unroll
                    for (int j0 = 0; j0 < 32; j0 += 4) {
                        float4 rv = *reinterpret_cast<const float4*>(rres + cb * 32 + j0);
                        v[j0+0] += rv.x; v[j0+1] += rv.y; v[j0+2] += rv.z; v[j0+3] += rv.w;
                    }
                }
                if constexpr (ACT == 1) {
                    #pragma unroll
                    for (int j = 0; j < 32; j++)
                        v[j] = 0.5f * v[j] * (1.0f + erff(v[j] * 0.70710678118654752f));
                }
                if constexpr (ROUND) {
                    #pragma unroll
                    for (int j = 0; j < 32; j++) v[j] = rna_tf32(v[j]);
                }
                #pragma unroll
                for (int j0 = 0; j0 < 32; j0 += 4) {
                    float4 o; o.x = v[j0]; o.y = v[j0+1]; o.z = v[j0+2]; o.w = v[j0+3];
                    *reinterpret_cast<float4*>(crow + cb * 32 + j0) = o;
                }
            }
            TC_FENCE_BEFORE();
            asm volatile("bar.sync 1, 128;" ::: "memory");
            if (tid == 0) mbar_arrive_leader(sb + OFF_TFREE(bank));
        }
    } else if (tid < 160) {
        // ---- TMA producer warp (one elected thread per CTA) ----
        if (elect_one()) {
            int s = 0; uint32_t eph = 1;
            for (int p = blockIdx.x >> 1; p < TP; p += (GRID / 2)) {
                const int tz = p / pgxy;
                const int rem = p - tz * pgxy;
                const int ty = rem / gx;
                const int tx = rem - ty * gx;
                const int ar = arow0 + rA * tz + ty * 256 + rank * 128;
                const int br = brow0 + rB * tz + tx * 256 + rank * 128;
                for (int kt = 0; kt < nk; kt++) {
                    mbar_wait(sb + OFF_EMPTY(s), eph);
                    const uint32_t st = sb + 1024 + s * STAGE_BYTES;
                    const uint32_t fb = sb + OFF_FULL(s);
                    if (rank == 0) mbar_expect_tx(fb, 131072);
                    const int k0 = kt * TK;
                    tma_cg2_2d(st,         &mapA, k0,      ar, fb);
                    tma_cg2_2d(st + 16384, &mapA, k0 + 32, ar, fb);
                    tma_cg2_2d(st + 32768, &mapB, k0,      br, fb);
                    tma_cg2_2d(st + 49152, &mapB, k0 + 32, br, fb);
                    if (++s == NS) { s = 0; eph ^= 1; }
                }
            }
        }
    } else {
        // ---- MMA issuer warp (leader CTA only) ----
        if (rank == 0) {
            uint32_t ep = elect_one();
            int s = 0; uint32_t ph = 0; int n = 0;
            for (int p = blockIdx.x >> 1; p < TP; p += (GRID / 2), n++) {
                const int bank = n & 1, nb = n >> 1;
                mbar_wait(sb + OFF_TFREE(bank), (nb + 1) & 1);
                TC_FENCE_AFTER();
                const uint32_t dstm = tmem + bank * 256;
                for (int kt = 0; kt < nk; kt++) {
                    mbar_wait(sb + OFF_FULL(s), ph);
                    if (ep) {
                        const uint32_t st = sb + 1024 + s * STAGE_BYTES;
                        const uint32_t en0 = (uint32_t)(kt != 0);
                        #pragma unroll
                        for (int h = 0; h < 2; h++) {
                            uint64_t ad = make_desc(st + h * 16384);
                            uint64_t bd = make_desc(st + 32768 + h * 16384);
                            #pragma unroll
                            for (int j = 0; j < 4; j++)
                                mma_tf32_cg2(dstm, ad + 2 * j, bd + 2 * j, IDESC2,
                                             en0 | (uint32_t)((h | j) != 0));
                        }
                        TC_COMMIT_MC_CG2(sb + OFF_EMPTY(s));
                        if (kt == nk - 1) TC_COMMIT_MC_CG2(sb + OFF_FIN(bank));
                    }
                    if (++s == NS) { s = 0; ph ^= 1; }
                }
            }
        }
    }

    __syncthreads();
    cluster_sync();      // no CTA exits while peer may still touch its smem/TMEM
    if (wid == 5) TC_DEALLOC_CG2(tmem, 512);
#endif // HAS_TC
}

// ---------------- elementwise kernels ---------------------------------------
__device__ __forceinline__ float block_sum(float v, float* sh) {
    const int lane = threadIdx.x & 31, w = threadIdx.x >> 5;
    #pragma unroll
    for (int o = 16; o; o >>= 1) v += __shfl_xor_sync(0xffffffffu, v, o);
    __syncthreads();
    if (lane == 0) sh[w] = v;
    __syncthreads();
    float s = 0.f;
    #pragma unroll
    for (int i = 0; i < 8; i++) s += sh[i];
    return s;
}
__device__ __forceinline__ float block_max(float v, float* sh) {
    const int lane = threadIdx.x & 31, w = threadIdx.x >> 5;
    #pragma unroll
    for (int o = 16; o; o >>= 1) v = fmaxf(v, __shfl_xor_sync(0xffffffffu, v, o));
    __syncthreads();
    if (lane == 0) sh[w] = v;
    __syncthreads();
    float s = -INFINITY;
    #pragma unroll
    for (int i = 0; i < 8; i++) s = fmaxf(s, sh[i]);
    return s;
}

__global__ void __launch_bounds__(256) softmax_kernel(float* __restrict__ data)
{
    __shared__ float sh[8];
    pdl_trigger();
    pdl_wait();
    const long long row = blockIdx.x;
    float4* p = reinterpret_cast<float4*>(data + row * 1024);
    float4 x = p[threadIdx.x];
    float m = fmaxf(fmaxf(x.x, x.y), fmaxf(x.z, x.w));
    m = block_max(m, sh);
    x.x = expf(x.x - m); x.y = expf(x.y - m);
    x.z = expf(x.z - m); x.w = expf(x.w - m);
    float s = x.x + x.y + x.z + x.w;
    s = block_sum(s, sh);
    const float inv = 1.0f / s;
    x.x = rna_tf32(x.x * inv); x.y = rna_tf32(x.y * inv);
    x.z = rna_tf32(x.z * inv); x.w = rna_tf32(x.w * inv);
    p[threadIdx.x] = x;
}

template<bool ROUND>
__global__ void __launch_bounds__(256)
ln_kernel(const float* __restrict__ in, const float* __restrict__ g,
          const float* __restrict__ b, float* __restrict__ out)
{
    __shared__ float sh[8];
    pdl_trigger();
    pdl_wait();
    const long long row = blockIdx.x;
    const float4* p = reinterpret_cast<const float4*>(in + row * 1024);
    float4 x = p[threadIdx.x];
    float s = x.x + x.y + x.z + x.w;
    s = block_sum(s, sh);
    const float mu = s * (1.0f / 1024.0f);
    const float dx = x.x - mu, dy = x.y - mu, dz = x.z - mu, dw = x.w - mu;
    float ss = dx * dx + dy * dy + dz * dz + dw * dw;
    ss = block_sum(ss, sh);
    const float rstd = rsqrtf(ss * (1.0f / 1024.0f) + 1e-12f);
    const float4 gg = reinterpret_cast<const float4*>(g)[threadIdx.x];
    const float4 bb = reinterpret_cast<const float4*>(b)[threadIdx.x];
    float4 o;
    o.x = dx * rstd * gg.x + bb.x;
    o.y = dy * rstd * gg.y + bb.y;
    o.z = dz * rstd * gg.z + bb.z;
    o.w = dw * rstd * gg.w + bb.w;
    if (ROUND) { o.x = rna_tf32(o.x); o.y = rna_tf32(o.y); o.z = rna_tf32(o.z); o.w = rna_tf32(o.w); }
    reinterpret_cast<float4*>(out + row * 1024)[threadIdx.x] = o;
}

// Fast 64x64 transpose body.
__device__ __forceinline__ void transpose_body(const float* __restrict__ in,
                                               float* __restrict__ out,
                                               int R, int C, int r0, int c0)
{
    __shared__ float t[64][65];
    const int fc = (threadIdx.x & 15) * 4;
    const int fr = threadIdx.x >> 4;

    #pragma unroll
    for (int i = 0; i < 4; i++) {
        const int r = fr + i * 16;
        float4 x = *reinterpret_cast<const float4*>(in + (long long)(r0 + r) * C + c0 + fc);
        t[fc + 0][r] = x.x; t[fc + 1][r] = x.y; t[fc + 2][r] = x.z; t[fc + 3][r] = x.w;
    }
    __syncthreads();
    #pragma unroll
    for (int i = 0; i < 4; i++) {
        const int oc = fr + i * 16;
        float4 y;
        y.x = rna_tf32(t[oc][fc + 0]); y.y = rna_tf32(t[oc][fc + 1]);
        y.z = rna_tf32(t[oc][fc + 2]); y.w = rna_tf32(t[oc][fc + 3]);
        *reinterpret_cast<float4*>(out + (long long)(c0 + oc) * R + r0 + fc) = y;
    }
}

__global__ void __launch_bounds__(256)
prep1_kernel(const float4* __restrict__ x, float4* __restrict__ xr, long long n4,
             const float4* __restrict__ bq, const float4* __restrict__ bk, float4* __restrict__ b2,
             const float* __restrict__ Wq, const float* __restrict__ Wk,
             const float* __restrict__ Wv, const float* __restrict__ Wd,
             float* __restrict__ oq, float* __restrict__ ok,
             float* __restrict__ ov, float* __restrict__ od)
{
    pdl_trigger();
    const int b = blockIdx.x;
    if (b < 1024) {
        for (long long i = b * 256LL + threadIdx.x; i < n4; i += 1024LL * 256LL) {
            float4 v = x[i];
            v.x = rna_tf32(v.x); v.y = rna_tf32(v.y);
            v.z = rna_tf32(v.z); v.w = rna_tf32(v.w);
            xr[i] = v;
        }
    } else if (b < 1026) {
        const float4* src = (b == 1024) ? bq : bk;
        b2[(b - 1024) * 256 + threadIdx.x] = src[threadIdx.x];
    } else {
        const int idx = b - 1026;
        const int w = idx >> 8;
        const int r = (idx & 255) >> 4;
        const int c = idx & 15;
        const float* in = w == 0 ? Wq : w == 1 ? Wk : w == 2 ? Wv : Wd;
        float* out      = w == 0 ? oq : w == 1 ? ok : w == 2 ? ov : od;
        transpose_body(in, out, 1024, 1024, r * 64, c * 64);
    }
}

__global__ void __launch_bounds__(256)
prep2_kernel(const float* __restrict__ Wi, float* __restrict__ wit,
             const float* __restrict__ Wo, float* __restrict__ wot)
{
    pdl_trigger();
    const int b = blockIdx.x;
    if (b < 1024) {
        const int cx = b & 63, ry = b >> 6;
        transpose_body(Wi, wit, Ed, Fd, ry * 64, cx * 64);
    } else {
        const int idx = b - 1024;
        const int cx = idx & 15, ry = idx >> 4;
        transpose_body(Wo, wot, Fd, Ed, ry * 64, cx * 64);
    }
}

// ---------------- host launcher -----------------------------------------------
typedef CUresult (*PFN_encode)(CUtensorMap*, CUtensorMapDataType, cuuint32_t, void*,
                               const cuuint64_t*, const cuuint64_t*, const cuuint32_t*,
                               const cuuint32_t*, CUtensorMapInterleave, CUtensorMapSwizzle,
                               CUtensorMapL2promotion, CUtensorMapFloatOOBfill);

static void enc2d(PFN_encode f, CUtensorMap* m, void* base, cuuint64_t K, cuuint64_t rows)
{
    cuuint64_t dims[2]    = {K, rows};
    cuuint64_t strides[1] = {K * 4};
    cuuint32_t box[2]     = {32, 128};
    cuuint32_t es[2]      = {1, 1};
    f(m, CU_TENSOR_MAP_DATA_TYPE_FLOAT32, 2, base, dims, strides, box, es,
      CU_TENSOR_MAP_INTERLEAVE_NONE, CU_TENSOR_MAP_SWIZZLE_128B,
      CU_TENSOR_MAP_L2_PROMOTION_L2_128B, CU_TENSOR_MAP_FLOAT_OOB_FILL_NONE);
}

extern "C" void kernel_launch(void* const* d_in, const int* in_sizes, int n_in,
                              void* d_out, int out_size)
{
    const float* x  = (const float*)d_in[0];
    const float* Wq = (const float*)d_in[1];
    const float* bq = (const float*)d_in[2];
    const float* Wk = (const float*)d_in[3];
    const float* bk = (const float*)d_in[4];
    const float* Wv = (const float*)d_in[5];
    const float* bv = (const float*)d_in[6];
    const float* Wd = (const float*)d_in[7];
    const float* bd = (const float*)d_in[8];
    const float* g1 = (const float*)d_in[9];
    const float* b1 = (const float*)d_in[10];
    const float* Wi = (const float*)d_in[11];
    const float* bi = (const float*)d_in[12];
    const float* Wo = (const float*)d_in[13];
    const float* bo = (const float*)d_in[14];
    const float* g2 = (const float*)d_in[15];
    const float* b2 = (const float*)d_in[16];
    float* out = (float*)d_out;

    float *xr, *qk, *vt, *at, *ao, *tmp, *h1, *ff;
    float *wt, *b2qk, *wdt, *wit, *wot;
    cudaGetSymbolAddress((void**)&xr,   g_xr);
    cudaGetSymbolAddress((void**)&qk,   g_qk);
    cudaGetSymbolAddress((void**)&vt,   g_vt);
    cudaGetSymbolAddress((void**)&at,   g_at);
    cudaGetSymbolAddress((void**)&ao,   g_ao);
    cudaGetSymbolAddress((void**)&tmp,  g_tmp);
    cudaGetSymbolAddress((void**)&h1,   g_h1);
    cudaGetSymbolAddress((void**)&ff,   g_ff);
    cudaGetSymbolAddress((void**)&wt,   g_wt);
    cudaGetSymbolAddress((void**)&b2qk, g_b2);
    cudaGetSymbolAddress((void**)&wdt,  g_wdt);
    cudaGetSymbolAddress((void**)&wit,  g_wit);
    cudaGetSymbolAddress((void**)&wot,  g_wot);

    cudaFuncSetAttribute(tc_gemm<0, true,  false>, cudaFuncAttributeMaxDynamicSharedMemorySize, SMEM_TOTAL);
    cudaFuncSetAttribute(tc_gemm<0, true,  true >, cudaFuncAttributeMaxDynamicSharedMemorySize, SMEM_TOTAL);
    cudaFuncSetAttribute(tc_gemm<0, false, false>, cudaFuncAttributeMaxDynamicSharedMemorySize, SMEM_TOTAL);
    cudaFuncSetAttribute(tc_gemm<1, true,  false>, cudaFuncAttributeMaxDynamicSharedMemorySize, SMEM_TOTAL);

    const long long ME = (long long)MTOT * Ed;
    const long long SE = (long long)Sd * Ed;
    const long long SS = (long long)Sd * Sd;
    const long long EE = (long long)Ed * Ed;

    // Tensormaps (driver API via dlopen)
    void* hdl = dlopen("libcuda.so.1", RTLD_LAZY | RTLD_GLOBAL);
    if (!hdl) hdl = dlopen("libcuda.so", RTLD_LAZY | RTLD_GLOBAL);
    PFN_encode enc = hdl ? (PFN_encode)dlsym(hdl, "cuTensorMapEncodeTiled") : nullptr;
    CUtensorMap mXr{}, mWt{}, mQk{}, mVt{}, mAt{}, mAo{}, mWdt{}, mH1{}, mWit{}, mFf{}, mWot{};
    enc2d(enc, &mXr,  xr,  1024, 8192);
    enc2d(enc, &mWt,  wt,  1024, 3072);
    enc2d(enc, &mQk,  qk,  1024, 16384);
    enc2d(enc, &mVt,  vt,  1024, 8192);
    enc2d(enc, &mAt,  at,  1024, 8192);
    enc2d(enc, &mAo,  ao,  1024, 8192);
    enc2d(enc, &mWdt, wdt, 1024, 1024);
    enc2d(enc, &mH1,  h1,  1024, 8192);
    enc2d(enc, &mWit, wit, 1024, 4096);
    enc2d(enc, &mFf,  ff,  4096, 8192);
    enc2d(enc, &mWot, wot, 4096, 1024);

    cudaLaunchAttribute pdlAttr[1];
    pdlAttr[0].id = cudaLaunchAttributeProgrammaticStreamSerialization;
    pdlAttr[0].val.programmaticStreamSerializationAllowed = 1;

    cudaLaunchAttribute clAttr[1];
    clAttr[0].id = cudaLaunchAttributeClusterDimension;
    clAttr[0].val.clusterDim.x = 2;
    clAttr[0].val.clusterDim.y = 1;
    clAttr[0].val.clusterDim.z = 1;

    auto launch = [&](auto kern, dim3 g, dim3 b, size_t sm,
                      cudaLaunchAttribute* attrs, int na, auto... args) {
        cudaLaunchConfig_t cfg{};
        cfg.gridDim = g; cfg.blockDim = b;
        cfg.dynamicSmemBytes = sm;
        cfg.stream = 0;
        cfg.attrs = attrs;
        cfg.numAttrs = na;
        cudaLaunchKernelEx(&cfg, kern, args...);
    };

    const float* nullf = nullptr;
    const dim3 gg(GRID);
    const dim3 gt(NTHREADS);

    // 0: prep1
    launch(prep1_kernel, dim3(2050), dim3(256), 0, nullptr, 0,
           (const float4*)x, (float4*)xr, (long long)(ME / 4),
           (const float4*)bq, (const float4*)bk, (float4*)b2qk,
           Wq, Wk, Wv, Wd, wt, wt + EE, wt + 2 * EE, wdt);
    // 1: prep2 (PDL co-run)
    launch(prep2_kernel, dim3(2048), dim3(256), 0, pdlAttr, 1, Wi, wit, Wo, wot);
    // 2: QK projections. A=xr, B=wt (rB=1024 selects Wq^T/Wk^T). T=256 tiles.
    launch(tc_gemm<0, true, false>, gg, gt, (size_t)SMEM_TOTAL, clAttr, 1,
           mXr, mWt, (const float*)b2qk, nullf, qk,
           (int)Ed, (int)Ed, 1.0f, ME, (long long)Ed, 0, 0, 0, 1024, 256, 4, 128);
    // 3: V^T = Wv^T @ xr^T + bv(row). A=wt rows[2048..], B=xr batched. T=128.
    launch(tc_gemm<0, true, true>, gg, gt, (size_t)SMEM_TOTAL, clAttr, 1,
           mWt, mXr, bv, nullf, vt,
           (int)Ed, (int)Sd, 1.0f, SE, 0LL, 2048, 0, 0, 1024, 128, 4, 16);
    // 4: scores = q @ k^T / 32. A=q (qk rows [0,8192)), B=k (rows [8192,16384)). T=128.
    launch(tc_gemm<0, false, false>, gg, gt, (size_t)SMEM_TOTAL, clAttr, 1,
           mQk, mQk, nullf, nullf, at,
           (int)Ed, (int)Sd, 0.03125f, SS, 0LL, 0, 1024, 8192, 1024, 128, 4, 16);
    // 5: softmax
    launch(softmax_kernel, dim3(Bd * Sd), dim3(256), 0, pdlAttr, 1, at);
    // 6: attn_out = attn_w @ v. A=at, B=vt, batched. T=128. K=Sd.
    launch(tc_gemm<0, true, false>, gg, gt, (size_t)SMEM_TOTAL, clAttr, 1,
           mAt, mVt, nullf, nullf, ao,
           (int)Sd, (int)Ed, 1.0f, SE, 0LL, 0, 1024, 0, 1024, 128, 4, 16);
    // 7: tmp = ao @ Wd + bd + x. T=128.
    launch(tc_gemm<0, false, false>, gg, gt, (size_t)SMEM_TOTAL, clAttr, 1,
           mAo, mWdt, bd, x, tmp,
           (int)Ed, (int)Ed, 1.0f, 0LL, 0LL, 0, 0, 0, 0, 128, 4, 128);
    // 8: h1 = LN(tmp)
    launch(ln_kernel<true>, dim3(MTOT), dim3(256), 0, pdlAttr, 1,
           (const float*)tmp, g1, b1, h1);
    // 9: ff = gelu(h1 @ Wi + bi). T=512.
    launch(tc_gemm<1, true, false>, gg, gt, (size_t)SMEM_TOTAL, clAttr, 1,
           mH1, mWit, bi, nullf, ff,
           (int)Ed, (int)Fd, 1.0f, 0LL, 0LL, 0, 0, 0, 0, 512, 16, 512);
    // 10: tmp = ff @ Wo + bo + h1. K=4096, T=128.
    launch(tc_gemm<0, false, false>, gg, gt, (size_t)SMEM_TOTAL, clAttr, 1,
           mFf, mWot, bo, (const float*)h1, tmp,
           (int)Fd, (int)Ed, 1.0f, 0LL, 0LL, 0, 0, 0, 0, 128, 4, 128);
    // 11: out = LN(tmp)
    launch(ln_kernel<false>, dim3(MTOT), dim3(256), 0, pdlAttr, 1,
           (const float*)tmp, g2, b2, out);
}

// round 17
// speedup vs baseline: 1.8117x; 1.5442x over previous
#include <cuda_runtime.h>
#include <cuda.h>
#include <cuda_fp16.h>
#include <math.h>
#include <stdint.h>
#include <dlfcn.h>

#if defined(__CUDA_ARCH_FEAT_SM103_ALL) || defined(__CUDA_ARCH_FEAT_SM100_ALL) || defined(__CUDA_ARCH_FEAT_SM101_ALL) || defined(__CUDA_ARCH_FEAT_SM110_ALL)
#define HAS_TC 1
#else
#define HAS_TC 0
#endif

// Problem dims
constexpr int Bd = 8;
constexpr int Sd = 1024;
constexpr int Ed = 1024;
constexpr int Fd = 4096;
constexpr int MTOT = Bd * Sd;   // 8192

// fp16 cg2 tile: 2-CTA cluster computes one 256x256 tile; M=256 dispatches.
// TK=128 fp16: per CTA per stage = A half (2x16KB panels) + B half (2x16KB) = 64KB.
constexpr int TK = 128;         // K elems per stage (two 64-elem SW128 fp16 panels)
constexpr int NS = 3;           // pipeline stages (64KB each)
constexpr int STAGE_BYTES = 65536;
constexpr int SMEM_TOTAL = 1024 + NS * STAGE_BYTES;     // 197632
constexpr int NTHREADS = 192;   // 4 epilogue warps + 1 TMA warp + 1 MMA warp
constexpr int GRID = 128;       // 64 clusters of 2, persistent

// idesc cg2 kind::f16: c=F32(1<<4), a=FP16(0), b=FP16(0), K-major, N=256, M=256
constexpr uint32_t IDESC16 =
    (1u << 4) | ((256 / 8) << 17) | ((256 / 16) << 24);

#define OFF_TMEM   0
#define OFF_FULL(s)   (8 + 8*(s))
#define OFF_EMPTY(s)  (8 + 8*NS + 8*(s))
#define OFF_FIN(b)    (8 + 16*NS + 8*(b))
#define OFF_TFREE(b)  (8 + 16*NS + 16 + 8*(b))

// ---------------- scratch (device globals) ---------------------------------
__device__ __half g_xr  [(long long)MTOT * Ed];
__device__ __half g_qk  [(long long)2 * MTOT * Ed];   // q | k contiguous
__device__ __half g_vt  [(long long)MTOT * Ed];
__device__ __half g_at  [(long long)Bd * Sd * Sd];
__device__ __half g_ao  [(long long)MTOT * Ed];
__device__ float  g_tmp [(long long)MTOT * Ed];       // pre-LN, fp32
__device__ __half g_h1  [(long long)MTOT * Ed];
__device__ __half g_ff  [(long long)MTOT * Fd];
__device__ __half g_wt  [(long long)3 * Ed * Ed];     // Wq^T | Wk^T | Wv^T
__device__ float  g_b2  [2 * Ed];
__device__ __half g_wdt [(long long)Ed * Ed];
__device__ __half g_wit [(long long)Fd * Ed];
__device__ __half g_wot [(long long)Ed * Fd];

// ---------------- PDL helpers ---------------------------------------------------
__device__ __forceinline__ void pdl_trigger() {
#if (defined(__CUDA_ARCH__) && __CUDA_ARCH__ >= 900)
    cudaTriggerProgrammaticLaunchCompletion();
#endif
}
__device__ __forceinline__ void pdl_wait() {
#if (defined(__CUDA_ARCH__) && __CUDA_ARCH__ >= 900)
    cudaGridDependencySynchronize();
#endif
}

// ---------------- PTX helpers -------------------------------------------------
__device__ __forceinline__ uint32_t smem_u32(const void* p) {
    uint32_t a;
    asm("{ .reg .u64 t; cvta.to.shared.u64 t, %1; cvt.u32.u64 %0, t; }" : "=r"(a) : "l"(p));
    return a;
}
__device__ __forceinline__ uint32_t elect_one() {
    uint32_t p;
    asm volatile("{ .reg .pred p; elect.sync _|p, 0xFFFFFFFF; selp.b32 %0,1,0,p; }" : "=r"(p));
    return p;
}
__device__ __forceinline__ uint32_t ctarank() {
    uint32_t r;
    asm("mov.u32 %0, %%cluster_ctarank;" : "=r"(r));
    return r;
}
__device__ __forceinline__ void cluster_sync() {
    asm volatile("barrier.cluster.arrive.aligned;" ::: "memory");
    asm volatile("barrier.cluster.wait.aligned;" ::: "memory");
}
__device__ __forceinline__ void mbar_init(uint32_t a, uint32_t c) {
    asm volatile("mbarrier.init.shared.b64 [%0], %1;" :: "r"(a), "r"(c) : "memory");
}
__device__ __forceinline__ void mbar_expect_tx(uint32_t a, uint32_t bytes) {
    asm volatile("mbarrier.arrive.expect_tx.shared.b64 _, [%0], %1;"
                 :: "r"(a), "r"(bytes) : "memory");
}
__device__ __forceinline__ void mbar_arrive_leader(uint32_t a) {
    asm volatile(
        "{\n\t.reg .b32 ra;\n\t"
        "mapa.shared::cluster.u32 ra, %0, 0;\n\t"
        "mbarrier.arrive.shared::cluster.b64 _, [ra];\n\t}"
        :: "r"(a) : "memory");
}
__device__ __forceinline__ void mbar_wait(uint32_t a, uint32_t ph) {
    uint32_t done;
    asm volatile(
        "{\n\t.reg .pred p;\n\t"
        "mbarrier.try_wait.parity.acquire.cta.shared::cta.b64 p, [%1], %2;\n\t"
        "selp.b32 %0, 1, 0, p;\n\t}"
        : "=r"(done) : "r"(a), "r"(ph) : "memory");
    if (!done) {
        asm volatile(
            "{\n\t.reg .pred P1;\n\t"
            "WL%=:\n\t"
            "mbarrier.try_wait.parity.acquire.cta.shared::cta.b64 P1, [%0], %1, 0x989680;\n\t"
            "@P1 bra.uni WD%=;\n\t"
            "bra.uni WL%=;\n\t"
            "WD%=:\n\t}"
            :: "r"(a), "r"(ph) : "memory");
    }
}
// cg2 TMA 2D load: data to LOCAL smem, complete_tx to the LEADER's barrier.
__device__ __forceinline__ void tma_cg2_2d(uint32_t dst, const void* map,
                                           int x, int y, uint32_t mbar) {
    asm volatile(
        "{\n\t.reg .b32 lb;\n\t"
        "and.b32 lb, %4, 0xFEFFFFFF;\n\t"
        "cp.async.bulk.tensor.2d.cta_group::2.shared::cluster.global.tile.mbarrier::complete_tx::bytes "
        "[%0], [%1, {%2, %3}], [lb];\n\t}"
        :: "r"(dst), "l"(map), "r"(x), "r"(y), "r"(mbar)
        : "memory");
}
__device__ __forceinline__ uint64_t make_desc(uint32_t addr) {
    return 0x4000404000010000ULL | ((uint64_t)(addr >> 4) & 0x3FFF);
}

#if HAS_TC
__device__ __forceinline__ void mma_f16_cg2(uint32_t d, uint64_t ad, uint64_t bd,
                                            uint32_t idesc, uint32_t en) {
    asm volatile(
        "{\n\t.reg .pred p;\n\t"
        "setp.ne.u32 p, %4, 0;\n\t"
        "tcgen05.mma.cta_group::2.kind::f16 [%0], %1, %2, %3, "
        "{%5, %5, %5, %5, %5, %5, %5, %5}, p;\n\t}"
        :: "r"(d), "l"(ad), "l"(bd), "r"(idesc), "r"(en), "r"(0u)
        : "memory");
}
#define TC_ALLOC_CG2(sa, n)  asm volatile("tcgen05.alloc.cta_group::2.sync.aligned.shared::cta.b32 [%0], %1;" :: "r"(sa), "r"(n) : "memory")
#define TC_DEALLOC_CG2(t, n) asm volatile("tcgen05.dealloc.cta_group::2.sync.aligned.b32 %0, %1;" :: "r"(t), "r"(n))
#define TC_RELINQ_CG2()      asm volatile("tcgen05.relinquish_alloc_permit.cta_group::2.sync.aligned;")
#define TC_COMMIT_MC_CG2(mb) asm volatile("tcgen05.commit.cta_group::2.mbarrier::arrive::one.shared::cluster.multicast::cluster.b64 [%0], %1;" :: "r"(mb), "h"((uint16_t)0x3) : "memory")
#define TC_FENCE_AFTER()     asm volatile("tcgen05.fence::after_thread_sync;" ::: "memory")
#define TC_FENCE_BEFORE()    asm volatile("tcgen05.fence::before_thread_sync;" ::: "memory")
#define TC_WAIT_LD()         asm volatile("tcgen05.wait::ld.sync.aligned;" ::: "memory")

#define LDTM_X32(r, ta) \
    asm volatile( \
        "tcgen05.ld.sync.aligned.32x32b.x32.b32 " \
        "{%0, %1, %2, %3, %4, %5, %6, %7, " \
        " %8, %9, %10, %11, %12, %13, %14, %15, " \
        " %16, %17, %18, %19, %20, %21, %22, %23, " \
        " %24, %25, %26, %27, %28, %29, %30, %31}, [%32];" \
        : "=r"((r)[0]),  "=r"((r)[1]),  "=r"((r)[2]),  "=r"((r)[3]), \
          "=r"((r)[4]),  "=r"((r)[5]),  "=r"((r)[6]),  "=r"((r)[7]), \
          "=r"((r)[8]),  "=r"((r)[9]),  "=r"((r)[10]), "=r"((r)[11]), \
          "=r"((r)[12]), "=r"((r)[13]), "=r"((r)[14]), "=r"((r)[15]), \
          "=r"((r)[16]), "=r"((r)[17]), "=r"((r)[18]), "=r"((r)[19]), \
          "=r"((r)[20]), "=r"((r)[21]), "=r"((r)[22]), "=r"((r)[23]), \
          "=r"((r)[24]), "=r"((r)[25]), "=r"((r)[26]), "=r"((r)[27]), \
          "=r"((r)[28]), "=r"((r)[29]), "=r"((r)[30]), "=r"((r)[31]) \
        : "r"(ta))
#endif // HAS_TC

// ---------------- cg2 persistent warp-specialized FP16 GEMM --------------------
// One 256x256 tile per 2-CTA cluster; TK=128 fp16 stages; TMEM D ping-pong.
// rank r supplies A rows [bm+r*128,+128) and B rows [bn+r*128,+128).
// Producers: TMA-only, 4 box-{64,128} fp16 loads per CTA per stage;
// complete_tx -> leader FULL (count=1 = leader expect_tx; tx = 131072/stage).
// EMPTY: cg2 commit multicast per stage. FIN[bank] at tile end; TFREE[bank]
// (count 2) released by both epilogues -> next tile's MMA overlaps the drain.
// OUT16: C is fp16 (else fp32). RES: 0 none, 1 fp32 resid, 2 fp16 resid.
template<int ACT, int OUT16, int RES, int BROW>
__global__ void __launch_bounds__(NTHREADS, 1)
tc_gemm(const __grid_constant__ CUtensorMap mapA,
        const __grid_constant__ CUtensorMap mapB,
        const float* __restrict__ bias, const void* __restrict__ resid,
        void* __restrict__ C, int K, int N, float alpha,
        long long sC, long long sBias,
        int arow0, int rA, int brow0, int rB,
        int TP, int gx, int pgxy)
{
#if HAS_TC
    extern __shared__ char smem[];
    const uint32_t sb = smem_u32(smem);
    const int tid = threadIdx.x;
    const int wid = tid >> 5;
    const int nk = K / TK;
    const int rank = (int)ctarank();

    if (tid == 0) {
        for (int s = 0; s < NS; s++) {
            mbar_init(sb + OFF_FULL(s), 1);
            mbar_init(sb + OFF_EMPTY(s), 1);
        }
        mbar_init(sb + OFF_FIN(0), 1);
        mbar_init(sb + OFF_FIN(1), 1);
        mbar_init(sb + OFF_TFREE(0), 2);
        mbar_init(sb + OFF_TFREE(1), 2);
    }
    if (wid == 5) {
        TC_ALLOC_CG2(sb + OFF_TMEM, 512);       // 2 x 256-col D banks
        TC_RELINQ_CG2();
    }
    __syncthreads();
    uint32_t tmem;
    asm volatile("ld.shared.b32 %0, [%1];" : "=r"(tmem) : "r"(sb + OFF_TMEM));

    cluster_sync();
    pdl_trigger();
    pdl_wait();

    if (tid < 128) {
        // ---- epilogue: this CTA's 128 M-rows x 256 cols from bank (n&1) ----
        const int lane = tid & 31;
        const int sp = wid;                 // 0..3
        int n = 0;
        for (int p = blockIdx.x >> 1; p < TP; p += (GRID / 2), n++) {
            const int bank = n & 1, nb = n >> 1;
            mbar_wait(sb + OFF_FIN(bank), nb & 1);
            TC_FENCE_AFTER();
            const int tz = p / pgxy;
            const int rem = p - tz * pgxy;
            const int ty = rem / gx;
            const int tx = rem - ty * gx;
            const int bn = tx * 256;
            const long long rrowi = (long long)ty * 256 + rank * 128 + sp * 32 + lane;
            const long long off = (long long)tz * sC + rrowi * (long long)N + bn;
            const float* biasz = bias ? bias + (long long)tz * sBias : nullptr;
            float brv = 0.0f;
            if (BROW && biasz) brv = biasz[rrowi];
            const uint32_t tmb = tmem + bank * 256;

            #pragma unroll 1
            for (int cb = 0; cb < 8; cb++) {
                uint32_t r[32];
                LDTM_X32(r, tmb + cb * 32);
                TC_WAIT_LD();
                float v[32];
                #pragma unroll
                for (int j = 0; j < 32; j++) v[j] = __uint_as_float(r[j]) * alpha;
                if (biasz) {
                    if (BROW) {
                        #pragma unroll
                        for (int j = 0; j < 32; j++) v[j] += brv;
                    } else {
                        #pragma unroll
                        for (int j0 = 0; j0 < 32; j0 += 4) {
                            float4 bb = *reinterpret_cast<const float4*>(biasz + bn + cb * 32 + j0);
                            v[j0+0] += bb.x; v[j0+1] += bb.y; v[j0+2] += bb.z; v[j0+3] += bb.w;
                        }
                    }
                }
                if constexpr (RES == 1) {
                    const float* rr = (const float*)resid + off + cb * 32;
                    #pragma unroll
                    for (int j0 = 0; j0 < 32; j0 += 4) {
                        float4 rv = *reinterpret_cast<const float4*>(rr + j0);
                        v[j0+0] += rv.x; v[j0+1] += rv.y; v[j0+2] += rv.z; v[j0+3] += rv.w;
                    }
                } else if constexpr (RES == 2) {
                    const uint4* rp = reinterpret_cast<const uint4*>(
                        (const __half*)resid + off + cb * 32);
                    #pragma unroll
                    for (int q = 0; q < 4; q++) {
                        uint4 u = rp[q];
                        const __half2* hh = reinterpret_cast<const __half2*>(&u);
                        #pragma unroll
                        for (int m = 0; m < 4; m++) {
                            float2 f = __half22float2(hh[m]);
                            v[q*8 + m*2 + 0] += f.x;
                            v[q*8 + m*2 + 1] += f.y;
                        }
                    }
                }
                if constexpr (ACT == 1) {
                    #pragma unroll
                    for (int j = 0; j < 32; j++)
                        v[j] = 0.5f * v[j] * (1.0f + erff(v[j] * 0.70710678118654752f));
                }
                if constexpr (OUT16) {
                    __half2 hb[16];
                    #pragma unroll
                    for (int jj = 0; jj < 16; jj++)
                        hb[jj] = __floats2half2_rn(v[2*jj], v[2*jj+1]);
                    uint4* dst = reinterpret_cast<uint4*>((__half*)C + off + cb * 32);
                    const uint4* src = reinterpret_cast<const uint4*>(hb);
                    dst[0] = src[0]; dst[1] = src[1]; dst[2] = src[2]; dst[3] = src[3];
                } else {
                    float* frow = (float*)C + off + cb * 32;
                    #pragma unroll
                    for (int j0 = 0; j0 < 32; j0 += 4) {
                        float4 o; o.x = v[j0]; o.y = v[j0+1]; o.z = v[j0+2]; o.w = v[j0+3];
                        *reinterpret_cast<float4*>(frow + j0) = o;
                    }
                }
            }
            TC_FENCE_BEFORE();
            asm volatile("bar.sync 1, 128;" ::: "memory");
            if (tid == 0) mbar_arrive_leader(sb + OFF_TFREE(bank));
        }
    } else if (tid < 160) {
        // ---- TMA producer warp (one elected thread per CTA) ----
        if (elect_one()) {
            int s = 0; uint32_t eph = 1;
            for (int p = blockIdx.x >> 1; p < TP; p += (GRID / 2)) {
                const int tz = p / pgxy;
                const int rem = p - tz * pgxy;
                const int ty = rem / gx;
                const int tx = rem - ty * gx;
                const int ar = arow0 + rA * tz + ty * 256 + rank * 128;
                const int br = brow0 + rB * tz + tx * 256 + rank * 128;
                for (int kt = 0; kt < nk; kt++) {
                    mbar_wait(sb + OFF_EMPTY(s), eph);
                    const uint32_t st = sb + 1024 + s * STAGE_BYTES;
                    const uint32_t fb = sb + OFF_FULL(s);
                    if (rank == 0) mbar_expect_tx(fb, 131072);
                    const int k0 = kt * TK;          // element coords (fp16)
                    tma_cg2_2d(st,         &mapA, k0,      ar, fb);
                    tma_cg2_2d(st + 16384, &mapA, k0 + 64, ar, fb);
                    tma_cg2_2d(st + 32768, &mapB, k0,      br, fb);
                    tma_cg2_2d(st + 49152, &mapB, k0 + 64, br, fb);
                    if (++s == NS) { s = 0; eph ^= 1; }
                }
            }
        }
    } else {
        // ---- MMA issuer warp (leader CTA only) ----
        if (rank == 0) {
            uint32_t ep = elect_one();
            int s = 0; uint32_t ph = 0; int n = 0;
            for (int p = blockIdx.x >> 1; p < TP; p += (GRID / 2), n++) {
                const int bank = n & 1, nb = n >> 1;
                mbar_wait(sb + OFF_TFREE(bank), (nb + 1) & 1);
                TC_FENCE_AFTER();
                const uint32_t dstm = tmem + bank * 256;
                for (int kt = 0; kt < nk; kt++) {
                    mbar_wait(sb + OFF_FULL(s), ph);
                    if (ep) {
                        const uint32_t st = sb + 1024 + s * STAGE_BYTES;
                        const uint32_t en0 = (uint32_t)(kt != 0);
                        #pragma unroll
                        for (int h = 0; h < 2; h++) {
                            uint64_t ad = make_desc(st + h * 16384);
                            uint64_t bd = make_desc(st + 32768 + h * 16384);
                            #pragma unroll
                            for (int j = 0; j < 4; j++)
                                mma_f16_cg2(dstm, ad + 2 * j, bd + 2 * j, IDESC16,
                                            en0 | (uint32_t)((h | j) != 0));
                        }
                        TC_COMMIT_MC_CG2(sb + OFF_EMPTY(s));
                        if (kt == nk - 1) TC_COMMIT_MC_CG2(sb + OFF_FIN(bank));
                    }
                    if (++s == NS) { s = 0; ph ^= 1; }
                }
            }
        }
    }

    __syncthreads();
    cluster_sync();
    if (wid == 5) TC_DEALLOC_CG2(tmem, 512);
#endif // HAS_TC
}

// ---------------- elementwise kernels ---------------------------------------
__device__ __forceinline__ float block_sum(float v, float* sh) {
    const int lane = threadIdx.x & 31, w = threadIdx.x >> 5;
    #pragma unroll
    for (int o = 16; o; o >>= 1) v += __shfl_xor_sync(0xffffffffu, v, o);
    __syncthreads();
    if (lane == 0) sh[w] = v;
    __syncthreads();
    float s = 0.f;
    #pragma unroll
    for (int i = 0; i < 8; i++) s += sh[i];
    return s;
}
__device__ __forceinline__ float block_max(float v, float* sh) {
    const int lane = threadIdx.x & 31, w = threadIdx.x >> 5;
    #pragma unroll
    for (int o = 16; o; o >>= 1) v = fmaxf(v, __shfl_xor_sync(0xffffffffu, v, o));
    __syncthreads();
    if (lane == 0) sh[w] = v;
    __syncthreads();
    float s = -INFINITY;
    #pragma unroll
    for (int i = 0; i < 8; i++) s = fmaxf(s, sh[i]);
    return s;
}

// softmax over fp16 rows of 1024 (in place)
__global__ void __launch_bounds__(256) softmax_kernel(__half* __restrict__ data)
{
    __shared__ float sh[8];
    pdl_trigger();
    pdl_wait();
    const long long row = blockIdx.x;
    __half2* p = reinterpret_cast<__half2*>(data + row * 1024);
    const int t = threadIdx.x;
    __half2 a = p[2*t], b = p[2*t + 1];
    float2 fa = __half22float2(a), fb = __half22float2(b);
    float m = fmaxf(fmaxf(fa.x, fa.y), fmaxf(fb.x, fb.y));
    m = block_max(m, sh);
    fa.x = expf(fa.x - m); fa.y = expf(fa.y - m);
    fb.x = expf(fb.x - m); fb.y = expf(fb.y - m);
    float s = fa.x + fa.y + fb.x + fb.y;
    s = block_sum(s, sh);
    const float inv = 1.0f / s;
    p[2*t]     = __floats2half2_rn(fa.x * inv, fa.y * inv);
    p[2*t + 1] = __floats2half2_rn(fb.x * inv, fb.y * inv);
}

// LayerNorm: fp32 in; OUT16 ? fp16 out : fp32 out
template<bool OUT16>
__global__ void __launch_bounds__(256)
ln_kernel(const float* __restrict__ in, const float* __restrict__ g,
          const float* __restrict__ b, void* __restrict__ outv)
{
    __shared__ float sh[8];
    pdl_trigger();
    pdl_wait();
    const long long row = blockIdx.x;
    const float4* p = reinterpret_cast<const float4*>(in + row * 1024);
    float4 x = p[threadIdx.x];
    float s = x.x + x.y + x.z + x.w;
    s = block_sum(s, sh);
    const float mu = s * (1.0f / 1024.0f);
    const float dx = x.x - mu, dy = x.y - mu, dz = x.z - mu, dw = x.w - mu;
    float ss = dx * dx + dy * dy + dz * dz + dw * dw;
    ss = block_sum(ss, sh);
    const float rstd = rsqrtf(ss * (1.0f / 1024.0f) + 1e-12f);
    const float4 gg = reinterpret_cast<const float4*>(g)[threadIdx.x];
    const float4 bb = reinterpret_cast<const float4*>(b)[threadIdx.x];
    float4 o;
    o.x = dx * rstd * gg.x + bb.x;
    o.y = dy * rstd * gg.y + bb.y;
    o.z = dz * rstd * gg.z + bb.z;
    o.w = dw * rstd * gg.w + bb.w;
    if constexpr (OUT16) {
        __half2 h0 = __floats2half2_rn(o.x, o.y);
        __half2 h1v = __floats2half2_rn(o.z, o.w);
        uint2 u;
        u.x = *reinterpret_cast<uint32_t*>(&h0);
        u.y = *reinterpret_cast<uint32_t*>(&h1v);
        reinterpret_cast<uint2*>((__half*)outv + row * 1024)[threadIdx.x] = u;
    } else {
        reinterpret_cast<float4*>((float*)outv + row * 1024)[threadIdx.x] = o;
    }
}

// Fast 64x64 transpose body (fp32 in -> fp16 out).
__device__ __forceinline__ void transpose_body(const float* __restrict__ in,
                                               __half* __restrict__ out,
                                               int R, int C, int r0, int c0)
{
    __shared__ float t[64][65];
    const int fc = (threadIdx.x & 15) * 4;
    const int fr = threadIdx.x >> 4;

    #pragma unroll
    for (int i = 0; i < 4; i++) {
        const int r = fr + i * 16;
        float4 x = *reinterpret_cast<const float4*>(in + (long long)(r0 + r) * C + c0 + fc);
        t[fc + 0][r] = x.x; t[fc + 1][r] = x.y; t[fc + 2][r] = x.z; t[fc + 3][r] = x.w;
    }
    __syncthreads();
    #pragma unroll
    for (int i = 0; i < 4; i++) {
        const int oc = fr + i * 16;
        __half2 h0 = __floats2half2_rn(t[oc][fc + 0], t[oc][fc + 1]);
        __half2 h1v = __floats2half2_rn(t[oc][fc + 2], t[oc][fc + 3]);
        uint2 u;
        u.x = *reinterpret_cast<uint32_t*>(&h0);
        u.y = *reinterpret_cast<uint32_t*>(&h1v);
        *reinterpret_cast<uint2*>(out + (long long)(c0 + oc) * R + r0 + fc) = u;
    }
}

__global__ void __launch_bounds__(256)
prep1_kernel(const float4* __restrict__ x, __half* __restrict__ xr, long long n4,
             const float4* __restrict__ bq, const float4* __restrict__ bk, float4* __restrict__ b2,
             const float* __restrict__ Wq, const float* __restrict__ Wk,
             const float* __restrict__ Wv, const float* __restrict__ Wd,
             __half* __restrict__ oq, __half* __restrict__ ok,
             __half* __restrict__ ov, __half* __restrict__ od)
{
    pdl_trigger();
    const int b = blockIdx.x;
    if (b < 1024) {
        for (long long i = b * 256LL + threadIdx.x; i < n4; i += 1024LL * 256LL) {
            float4 v = x[i];
            __half2 h0 = __floats2half2_rn(v.x, v.y);
            __half2 h1v = __floats2half2_rn(v.z, v.w);
            uint2 u;
            u.x = *reinterpret_cast<uint32_t*>(&h0);
            u.y = *reinterpret_cast<uint32_t*>(&h1v);
            reinterpret_cast<uint2*>(xr)[i] = u;
        }
    } else if (b < 1026) {
        const float4* src = (b == 1024) ? bq : bk;
        b2[(b - 1024) * 256 + threadIdx.x] = src[threadIdx.x];
    } else {
        const int idx = b - 1026;
        const int w = idx >> 8;
        const int r = (idx & 255) >> 4;
        const int c = idx & 15;
        const float* in = w == 0 ? Wq : w == 1 ? Wk : w == 2 ? Wv : Wd;
        __half* out     = w == 0 ? oq : w == 1 ? ok : w == 2 ? ov : od;
        transpose_body(in, out, 1024, 1024, r * 64, c * 64);
    }
}

__global__ void __launch_bounds__(256)
prep2_kernel(const float* __restrict__ Wi, __half* __restrict__ wit,
             const float* __restrict__ Wo, __half* __restrict__ wot)
{
    pdl_trigger();
    const int b = blockIdx.x;
    if (b < 1024) {
        const int cx = b & 63, ry = b >> 6;
        transpose_body(Wi, wit, Ed, Fd, ry * 64, cx * 64);
    } else {
        const int idx = b - 1024;
        const int cx = idx & 15, ry = idx >> 4;
        transpose_body(Wo, wot, Fd, Ed, ry * 64, cx * 64);
    }
}

// ---------------- host launcher -----------------------------------------------
typedef CUresult (*PFN_encode)(CUtensorMap*, CUtensorMapDataType, cuuint32_t, void*,
                               const cuuint64_t*, const cuuint64_t*, const cuuint32_t*,
                               const cuuint32_t*, CUtensorMapInterleave, CUtensorMapSwizzle,
                               CUtensorMapL2promotion, CUtensorMapFloatOOBfill);

static void enc2d16(PFN_encode f, CUtensorMap* m, void* base, cuuint64_t K, cuuint64_t rows)
{
    cuuint64_t dims[2]    = {K, rows};
    cuuint64_t strides[1] = {K * 2};
    cuuint32_t box[2]     = {64, 128};   // 64 fp16 = 128B = SW128 atom
    cuuint32_t es[2]      = {1, 1};
    f(m, CU_TENSOR_MAP_DATA_TYPE_FLOAT16, 2, base, dims, strides, box, es,
      CU_TENSOR_MAP_INTERLEAVE_NONE, CU_TENSOR_MAP_SWIZZLE_128B,
      CU_TENSOR_MAP_L2_PROMOTION_L2_128B, CU_TENSOR_MAP_FLOAT_OOB_FILL_NONE);
}

extern "C" void kernel_launch(void* const* d_in, const int* in_sizes, int n_in,
                              void* d_out, int out_size)
{
    const float* x  = (const float*)d_in[0];
    const float* Wq = (const float*)d_in[1];
    const float* bq = (const float*)d_in[2];
    const float* Wk = (const float*)d_in[3];
    const float* bk = (const float*)d_in[4];
    const float* Wv = (const float*)d_in[5];
    const float* bv = (const float*)d_in[6];
    const float* Wd = (const float*)d_in[7];
    const float* bd = (const float*)d_in[8];
    const float* g1 = (const float*)d_in[9];
    const float* b1 = (const float*)d_in[10];
    const float* Wi = (const float*)d_in[11];
    const float* bi = (const float*)d_in[12];
    const float* Wo = (const float*)d_in[13];
    const float* bo = (const float*)d_in[14];
    const float* g2 = (const float*)d_in[15];
    const float* b2 = (const float*)d_in[16];
    float* out = (float*)d_out;

    __half *xr, *qk, *vt, *at, *ao, *h1, *ff, *wt, *wdt, *wit, *wot;
    float *tmp, *b2qk;
    cudaGetSymbolAddress((void**)&xr,   g_xr);
    cudaGetSymbolAddress((void**)&qk,   g_qk);
    cudaGetSymbolAddress((void**)&vt,   g_vt);
    cudaGetSymbolAddress((void**)&at,   g_at);
    cudaGetSymbolAddress((void**)&ao,   g_ao);
    cudaGetSymbolAddress((void**)&tmp,  g_tmp);
    cudaGetSymbolAddress((void**)&h1,   g_h1);
    cudaGetSymbolAddress((void**)&ff,   g_ff);
    cudaGetSymbolAddress((void**)&wt,   g_wt);
    cudaGetSymbolAddress((void**)&b2qk, g_b2);
    cudaGetSymbolAddress((void**)&wdt,  g_wdt);
    cudaGetSymbolAddress((void**)&wit,  g_wit);
    cudaGetSymbolAddress((void**)&wot,  g_wot);

    cudaFuncSetAttribute(tc_gemm<0, 1, 0, 0>, cudaFuncAttributeMaxDynamicSharedMemorySize, SMEM_TOTAL);
    cudaFuncSetAttribute(tc_gemm<0, 1, 0, 1>, cudaFuncAttributeMaxDynamicSharedMemorySize, SMEM_TOTAL);
    cudaFuncSetAttribute(tc_gemm<0, 0, 1, 0>, cudaFuncAttributeMaxDynamicSharedMemorySize, SMEM_TOTAL);
    cudaFuncSetAttribute(tc_gemm<1, 1, 0, 0>, cudaFuncAttributeMaxDynamicSharedMemorySize, SMEM_TOTAL);
    cudaFuncSetAttribute(tc_gemm<0, 0, 2, 0>, cudaFuncAttributeMaxDynamicSharedMemorySize, SMEM_TOTAL);

    const long long ME = (long long)MTOT * Ed;
    const long long SE = (long long)Sd * Ed;
    const long long SS = (long long)Sd * Sd;
    const long long EE = (long long)Ed * Ed;

    // Tensormaps (driver API via dlopen)
    void* hdl = dlopen("libcuda.so.1", RTLD_LAZY | RTLD_GLOBAL);
    if (!hdl) hdl = dlopen("libcuda.so", RTLD_LAZY | RTLD_GLOBAL);
    PFN_encode enc = hdl ? (PFN_encode)dlsym(hdl, "cuTensorMapEncodeTiled") : nullptr;
    CUtensorMap mXr{}, mWt{}, mQk{}, mVt{}, mAt{}, mAo{}, mWdt{}, mH1{}, mWit{}, mFf{}, mWot{};
    enc2d16(enc, &mXr,  xr,  1024, 8192);
    enc2d16(enc, &mWt,  wt,  1024, 3072);
    enc2d16(enc, &mQk,  qk,  1024, 16384);
    enc2d16(enc, &mVt,  vt,  1024, 8192);
    enc2d16(enc, &mAt,  at,  1024, 8192);
    enc2d16(enc, &mAo,  ao,  1024, 8192);
    enc2d16(enc, &mWdt, wdt, 1024, 1024);
    enc2d16(enc, &mH1,  h1,  1024, 8192);
    enc2d16(enc, &mWit, wit, 1024, 4096);
    enc2d16(enc, &mFf,  ff,  4096, 8192);
    enc2d16(enc, &mWot, wot, 4096, 1024);

    cudaLaunchAttribute pdlAttr[1];
    pdlAttr[0].id = cudaLaunchAttributeProgrammaticStreamSerialization;
    pdlAttr[0].val.programmaticStreamSerializationAllowed = 1;

    cudaLaunchAttribute clAttr[1];
    clAttr[0].id = cudaLaunchAttributeClusterDimension;
    clAttr[0].val.clusterDim.x = 2;
    clAttr[0].val.clusterDim.y = 1;
    clAttr[0].val.clusterDim.z = 1;

    auto launch = [&](auto kern, dim3 g, dim3 b, size_t sm,
                      cudaLaunchAttribute* attrs, int na, auto... args) {
        cudaLaunchConfig_t cfg{};
        cfg.gridDim = g; cfg.blockDim = b;
        cfg.dynamicSmemBytes = sm;
        cfg.stream = 0;
        cfg.attrs = attrs;
        cfg.numAttrs = na;
        cudaLaunchKernelEx(&cfg, kern, args...);
    };

    const void* nullv = nullptr;
    const float* nullf = nullptr;
    const dim3 gg(GRID);
    const dim3 gt(NTHREADS);

    // 0: prep1 (x -> fp16 xr, bias concat, Wq/Wk/Wv/Wd transposes -> fp16)
    launch(prep1_kernel, dim3(2050), dim3(256), 0, nullptr, 0,
           (const float4*)x, xr, (long long)(ME / 4),
           (const float4*)bq, (const float4*)bk, (float4*)b2qk,
           Wq, Wk, Wv, Wd, wt, wt + EE, wt + 2 * EE, wdt);
    // 1: prep2 (Wi/Wo transposes -> fp16; PDL co-run)
    launch(prep2_kernel, dim3(2048), dim3(256), 0, pdlAttr, 1, Wi, wit, Wo, wot);
    // 2: QK projections. A=xr, B=wt (rB=1024 selects Wq^T/Wk^T). T=256.
    launch(tc_gemm<0, 1, 0, 0>, gg, gt, (size_t)SMEM_TOTAL, clAttr, 1,
           mXr, mWt, (const float*)b2qk, nullv, (void*)qk,
           (int)Ed, (int)Ed, 1.0f, ME, (long long)Ed, 0, 0, 0, 1024, 256, 4, 128);
    // 3: V^T = Wv^T @ xr^T + bv(row). A=wt rows[2048..], B=xr batched. T=128.
    launch(tc_gemm<0, 1, 0, 1>, gg, gt, (size_t)SMEM_TOTAL, clAttr, 1,
           mWt, mXr, bv, nullv, (void*)vt,
           (int)Ed, (int)Sd, 1.0f, SE, 0LL, 2048, 0, 0, 1024, 128, 4, 16);
    // 4: scores = q @ k^T / 32. A=q (rows [0,8192)), B=k (rows [8192,16384)). T=128.
    launch(tc_gemm<0, 1, 0, 0>, gg, gt, (size_t)SMEM_TOTAL, clAttr, 1,
           mQk, mQk, nullf, nullv, (void*)at,
           (int)Ed, (int)Sd, 0.03125f, SS, 0LL, 0, 1024, 8192, 1024, 128, 4, 16);
    // 5: softmax (fp16 in place)
    launch(softmax_kernel, dim3(Bd * Sd), dim3(256), 0, pdlAttr, 1, at);
    // 6: attn_out = attn_w @ v. A=at, B=vt, batched. T=128. K=Sd.
    launch(tc_gemm<0, 1, 0, 0>, gg, gt, (size_t)SMEM_TOTAL, clAttr, 1,
           mAt, mVt, nullf, nullv, (void*)ao,
           (int)Sd, (int)Ed, 1.0f, SE, 0LL, 0, 1024, 0, 1024, 128, 4, 16);
    // 7: tmp = ao @ Wd + bd + x (fp32 resid, fp32 out). T=128.
    launch(tc_gemm<0, 0, 1, 0>, gg, gt, (size_t)SMEM_TOTAL, clAttr, 1,
           mAo, mWdt, bd, (const void*)x, (void*)tmp,
           (int)Ed, (int)Ed, 1.0f, 0LL, 0LL, 0, 0, 0, 0, 128, 4, 128);
    // 8: h1 = LN(tmp) -> fp16
    launch(ln_kernel<true>, dim3(MTOT), dim3(256), 0, pdlAttr, 1,
           (const float*)tmp, g1, b1, (void*)h1);
    // 9: ff = gelu(h1 @ Wi + bi) -> fp16. T=512.
    launch(tc_gemm<1, 1, 0, 0>, gg, gt, (size_t)SMEM_TOTAL, clAttr, 1,
           mH1, mWit, bi, nullv, (void*)ff,
           (int)Ed, (int)Fd, 1.0f, 0LL, 0LL, 0, 0, 0, 0, 512, 16, 512);
    // 10: tmp = ff @ Wo + bo + h1 (fp16 resid, fp32 out). K=4096, T=128.
    launch(tc_gemm<0, 0, 2, 0>, gg, gt, (size_t)SMEM_TOTAL, clAttr, 1,
           mFf, mWot, bo, (const void*)h1, (void*)tmp,
           (int)Fd, (int)Ed, 1.0f, 0LL, 0LL, 0, 0, 0, 0, 128, 4, 128);
    // 11: out = LN(tmp) -> fp32
    launch(ln_kernel<false>, dim3(MTOT), dim3(256), 0, pdlAttr, 1,
           (const float*)tmp, g2, b2, (void*)out);
}